// round 1
// baseline (speedup 1.0000x reference)
#include <cuda_runtime.h>

#define B_  32
#define S_  512
#define D_  256
#define F_  256
#define K_  3
#define BS_ (B_*S_)        // 16384
#define KK_ (D_*K_)        // 768

// Scratch (device globals: allocation-free, allowed by harness rules)
__device__ float g_h1[BS_*F_];        // 16 MB
__device__ float g_h2[BS_*F_];        // 16 MB
__device__ float g_w1t[KK_*F_];       // transposed conv1 weight [kk][f]
__device__ float g_w2t[KK_*F_];
__device__ int   g_rowmap[B_*4608];   // l -> s map per batch (L <= 4096)

// ---------------------------------------------------------------------------
// Weight transpose: wt[(k*256+c)*256 + f] = w[f*768 + c*3 + k]
// (k-major kk so GEMM B-tile loads are fully coalesced and each BK=16 chunk
//  sits inside a single shift k)
// ---------------------------------------------------------------------------
template<int PH>
__global__ void transpose_w_k(const float* __restrict__ w) {
    float* wt = (PH == 0) ? g_w1t : g_w2t;
    int idx = blockIdx.x * blockDim.x + threadIdx.x;
    if (idx >= KK_ * F_) return;
    int f  = idx & 255;
    int kk = idx >> 8;         // kk = k*256 + c
    int c  = kk & 255;
    int k  = kk >> 8;
    wt[idx] = w[f * KK_ + c * K_ + k];
}

// ---------------------------------------------------------------------------
// Conv-as-GEMM: C[bs, f] = sum_kk A[b, s+k-1, c] * Wt[kk, f] + bias[f]
// 128x128 tile, BK=16, 256 threads, 8x8 micro-tile per thread.
// PH=0: A = x (input), C = g_h1 ; PH=1: A = g_h1, C = g_h2
// ---------------------------------------------------------------------------
template<int PH>
__global__ __launch_bounds__(256) void conv_gemm_k(const float* __restrict__ Xin,
                                                   const float* __restrict__ bias) {
    const float* A  = (PH == 0) ? Xin   : g_h1;
    const float* Wt = (PH == 0) ? g_w1t : g_w2t;
    float*       C  = (PH == 0) ? g_h1  : g_h2;

    __shared__ float As[16][132];   // [kk][m], padded
    __shared__ float Bs[16][132];   // [kk][f], padded

    const int tid     = threadIdx.x;
    const int rowBase = blockIdx.x * 128;
    const int colBase = blockIdx.y * 128;

    const int tx = tid & 15;         // 0..15 -> 8 cols each
    const int ty = tid >> 4;         // 0..15 -> 8 rows each
    const int la_row = tid >> 2;     // 0..63
    const int la_k4  = (tid & 3) << 2;
    const int lb_kk  = tid >> 5;     // 0..7
    const int lb_f4  = (tid & 31) << 2;

    float acc[8][8];
    #pragma unroll
    for (int i = 0; i < 8; i++)
        #pragma unroll
        for (int j = 0; j < 8; j++) acc[i][j] = 0.f;

    for (int kk0 = 0; kk0 < KK_; kk0 += 16) {
        const int k3 = kk0 >> 8;     // shift index 0..2 (constant in chunk)
        const int c0 = kk0 & 255;

        // ---- load A tile (im2col with 'same' zero padding at s boundaries)
        #pragma unroll
        for (int rr = 0; rr < 2; ++rr) {
            int r  = rowBase + la_row + rr * 64;      // global bs row
            int s  = r & 511;
            int sp = s + k3 - 1;
            float4 v = make_float4(0.f, 0.f, 0.f, 0.f);
            if ((unsigned)sp < 512u)
                v = *reinterpret_cast<const float4*>(
                        A + (size_t)(r - s + sp) * D_ + c0 + la_k4);
            int m = la_row + rr * 64;
            As[la_k4 + 0][m] = v.x;
            As[la_k4 + 1][m] = v.y;
            As[la_k4 + 2][m] = v.z;
            As[la_k4 + 3][m] = v.w;
        }
        // ---- load B tile (coalesced)
        #pragma unroll
        for (int rr = 0; rr < 2; ++rr) {
            int kk = lb_kk + rr * 8;
            *reinterpret_cast<float4*>(&Bs[kk][lb_f4]) =
                *reinterpret_cast<const float4*>(
                    Wt + (size_t)(kk0 + kk) * F_ + colBase + lb_f4);
        }
        __syncthreads();

        #pragma unroll
        for (int kk = 0; kk < 16; ++kk) {
            float a[8], b[8];
            #pragma unroll
            for (int i = 0; i < 8; i++) a[i] = As[kk][ty * 8 + i];
            #pragma unroll
            for (int j = 0; j < 8; j++) b[j] = Bs[kk][tx * 8 + j];
            #pragma unroll
            for (int i = 0; i < 8; i++)
                #pragma unroll
                for (int j = 0; j < 8; j++)
                    acc[i][j] = fmaf(a[i], b[j], acc[i][j]);
        }
        __syncthreads();
    }

    #pragma unroll
    for (int i = 0; i < 8; i++) {
        size_t r = (size_t)(rowBase + ty * 8 + i);
        #pragma unroll
        for (int j = 0; j < 8; j += 4) {
            int f = colBase + tx * 8 + j;
            float4 v;
            v.x = acc[i][j + 0] + bias[f + 0];
            v.y = acc[i][j + 1] + bias[f + 1];
            v.z = acc[i][j + 2] + bias[f + 2];
            v.w = acc[i][j + 3] + bias[f + 3];
            *reinterpret_cast<float4*>(C + r * F_ + f) = v;
        }
    }
}

// ---------------------------------------------------------------------------
// LayerNorm(F=256) + ReLU, in place. One block (256 threads) per row.
// ---------------------------------------------------------------------------
__device__ __forceinline__ float block_sum_256(float v, float* shm) {
    int lane = threadIdx.x & 31, wp = threadIdx.x >> 5;
    #pragma unroll
    for (int o = 16; o > 0; o >>= 1) v += __shfl_xor_sync(0xffffffffu, v, o);
    if (lane == 0) shm[wp] = v;
    __syncthreads();
    float r = shm[lane & 7];   // 8 warps in a 256-thread block
    #pragma unroll
    for (int o = 4; o > 0; o >>= 1) r += __shfl_xor_sync(0xffffffffu, r, o);
    __syncthreads();           // safe to reuse shm after return
    return r;
}

template<int PH>
__global__ __launch_bounds__(256) void ln_relu_k(const float* __restrict__ g,
                                                 const float* __restrict__ be) {
    float* h = (PH == 0) ? g_h1 : g_h2;
    __shared__ float shm[8];
    size_t row = blockIdx.x;
    int tid = threadIdx.x;
    float v  = h[row * F_ + tid];
    float mu = block_sum_256(v, shm) * (1.f / 256.f);
    float d  = v - mu;
    float var = block_sum_256(d * d, shm) * (1.f / 256.f);
    float o = fmaxf(0.f, d * rsqrtf(var + 1e-5f) * g[tid] + be[tid]);
    h[row * F_ + tid] = o;
}

// ---------------------------------------------------------------------------
// Linear head: pred[bs] = relu(h2[bs,:] . lw + lb). One warp per row.
// ---------------------------------------------------------------------------
__global__ __launch_bounds__(256) void linear_k(const float* __restrict__ lw,
                                                const float* __restrict__ lb,
                                                float* __restrict__ pred) {
    int row  = blockIdx.x * 8 + (threadIdx.x >> 5);
    int lane = threadIdx.x & 31;
    const float* h = g_h2 + (size_t)row * F_;
    float s = 0.f;
    #pragma unroll
    for (int i = 0; i < 8; i++) s = fmaf(h[lane + i * 32], lw[lane + i * 32], s);
    #pragma unroll
    for (int o = 16; o > 0; o >>= 1) s += __shfl_xor_sync(0xffffffffu, s, o);
    if (lane == 0) pred[row] = fmaxf(0.f, s + lb[0]);
}

// ---------------------------------------------------------------------------
// Row map: per batch, d = rint(target); cumsum; rowmap[b*L + l] = s for
// l in [start, end), else -1. One block of 512 threads per batch.
// ---------------------------------------------------------------------------
__global__ __launch_bounds__(512) void rowmap_k(const float* __restrict__ target, int L) {
    int b = blockIdx.x, s = threadIdx.x;
    int lane = s & 31, wp = s >> 5;
    int d = (int)rintf(target[b * 512 + s]);   // round-half-even == jnp.round
    int v = d;
    #pragma unroll
    for (int o = 1; o < 32; o <<= 1) {
        int t = __shfl_up_sync(0xffffffffu, v, o);
        if (lane >= o) v += t;
    }
    __shared__ int wsum[16];
    if (lane == 31) wsum[wp] = v;
    __syncthreads();
    if (s < 16) {
        int w = wsum[s];
        #pragma unroll
        for (int o = 1; o < 16; o <<= 1) {
            int t = __shfl_up_sync(0x0000ffffu, w, o);
            if (s >= o) w += t;
        }
        wsum[s] = w;
    }
    __syncthreads();
    int end   = v + (wp ? wsum[wp - 1] : 0);
    int start = end - d;
    int* rm = g_rowmap + (size_t)b * L;
    for (int l = s; l < L; l += 512) rm[l] = -1;
    __syncthreads();
    if (start < L) {
        int e = min(end, L);
        for (int l = start; l < e; ++l) rm[l] = s;
    }
}

// ---------------------------------------------------------------------------
// Gather/expand: out[b, l, :] = (s>=0) ? x[b, s, :] : 0. 4 rows per block.
// ---------------------------------------------------------------------------
__global__ __launch_bounds__(256) void gather_k(const float* __restrict__ x,
                                                float* __restrict__ out, int L) {
    int rowId = blockIdx.x * 4 + (threadIdx.x >> 6);   // rowId == b*L + l
    if (rowId >= B_ * L) return;
    int t = threadIdx.x & 63;
    int b = rowId / L;
    int s = g_rowmap[rowId];
    float4 v = make_float4(0.f, 0.f, 0.f, 0.f);
    if (s >= 0)
        v = *reinterpret_cast<const float4*>(
                x + (size_t)((b << 9) + s) * D_ + (t << 2));
    *reinterpret_cast<float4*>(out + (size_t)rowId * D_ + (t << 2)) = v;
}

// ---------------------------------------------------------------------------
extern "C" void kernel_launch(void* const* d_in, const int* in_sizes, int n_in,
                              void* d_out, int out_size) {
    const float* x   = (const float*)d_in[0];
    const float* tgt = (const float*)d_in[1];
    const float* c1w = (const float*)d_in[2];
    const float* c1b = (const float*)d_in[3];
    const float* c2w = (const float*)d_in[4];
    const float* c2b = (const float*)d_in[5];
    const float* n1g = (const float*)d_in[6];
    const float* n1b = (const float*)d_in[7];
    const float* n2g = (const float*)d_in[8];
    const float* n2b = (const float*)d_in[9];
    const float* lw  = (const float*)d_in[10];
    const float* lb  = (const float*)d_in[11];

    float* out = (float*)d_out;
    // out = concat( expanded [B, L, D], predicted_len [B, S] )
    int L = (out_size - B_ * S_) / (B_ * D_);
    float* pred = out + (size_t)B_ * L * D_;

    transpose_w_k<0><<<(KK_ * F_ + 255) / 256, 256>>>(c1w);
    transpose_w_k<1><<<(KK_ * F_ + 255) / 256, 256>>>(c2w);

    conv_gemm_k<0><<<dim3(BS_ / 128, F_ / 128), 256>>>(x, c1b);
    ln_relu_k<0><<<BS_, 256>>>(n1g, n1b);
    conv_gemm_k<1><<<dim3(BS_ / 128, F_ / 128), 256>>>(x, c2b);
    ln_relu_k<1><<<BS_, 256>>>(n2g, n2b);
    linear_k<<<BS_ / 8, 256>>>(lw, lb, pred);

    rowmap_k<<<B_, 512>>>(tgt, L);
    gather_k<<<(B_ * L + 3) / 4, 256>>>(x, out, L);
}

// round 2
// speedup vs baseline: 1.0002x; 1.0002x over previous
#include <cuda_runtime.h>

#define B_  32
#define S_  512
#define D_  256
#define F_  256
#define K_  3
#define BS_ (B_*S_)        // 16384
#define KK_ (D_*K_)        // 768

// Scratch (device globals: allocation-free, allowed by harness rules)
__device__ float g_h1[BS_*F_];        // 16 MB
__device__ float g_h2[BS_*F_];        // 16 MB
__device__ float g_w1t[KK_*F_];       // transposed conv1 weight [kk][f]
__device__ float g_w2t[KK_*F_];
__device__ int   g_rowmap[B_*4608];   // l -> s map per batch (L <= 4096)

// ---------------------------------------------------------------------------
// Weight transpose: wt[(k*256+c)*256 + f] = w[f*768 + c*3 + k]
// (k-major kk so GEMM B-tile loads are fully coalesced and each BK=16 chunk
//  sits inside a single shift k)
// ---------------------------------------------------------------------------
template<int PH>
__global__ void transpose_w_k(const float* __restrict__ w) {
    float* wt = (PH == 0) ? g_w1t : g_w2t;
    int idx = blockIdx.x * blockDim.x + threadIdx.x;
    if (idx >= KK_ * F_) return;
    int f  = idx & 255;
    int kk = idx >> 8;         // kk = k*256 + c
    int c  = kk & 255;
    int k  = kk >> 8;
    wt[idx] = w[f * KK_ + c * K_ + k];
}

// ---------------------------------------------------------------------------
// Conv-as-GEMM: C[bs, f] = sum_kk A[b, s+k-1, c] * Wt[kk, f] + bias[f]
// 128x128 tile, BK=16, 256 threads, 8x8 micro-tile per thread.
// PH=0: A = x (input), C = g_h1 ; PH=1: A = g_h1, C = g_h2
// ---------------------------------------------------------------------------
template<int PH>
__global__ __launch_bounds__(256) void conv_gemm_k(const float* __restrict__ Xin,
                                                   const float* __restrict__ bias) {
    const float* A  = (PH == 0) ? Xin   : g_h1;
    const float* Wt = (PH == 0) ? g_w1t : g_w2t;
    float*       C  = (PH == 0) ? g_h1  : g_h2;

    __shared__ float As[16][132];   // [kk][m], padded
    __shared__ float Bs[16][132];   // [kk][f], padded

    const int tid     = threadIdx.x;
    const int rowBase = blockIdx.x * 128;
    const int colBase = blockIdx.y * 128;

    const int tx = tid & 15;         // 0..15 -> 8 cols each
    const int ty = tid >> 4;         // 0..15 -> 8 rows each
    const int la_row = tid >> 2;     // 0..63
    const int la_k4  = (tid & 3) << 2;
    const int lb_kk  = tid >> 5;     // 0..7
    const int lb_f4  = (tid & 31) << 2;

    float acc[8][8];
    #pragma unroll
    for (int i = 0; i < 8; i++)
        #pragma unroll
        for (int j = 0; j < 8; j++) acc[i][j] = 0.f;

    for (int kk0 = 0; kk0 < KK_; kk0 += 16) {
        const int k3 = kk0 >> 8;     // shift index 0..2 (constant in chunk)
        const int c0 = kk0 & 255;

        // ---- load A tile (im2col with 'same' zero padding at s boundaries)
        #pragma unroll
        for (int rr = 0; rr < 2; ++rr) {
            int r  = rowBase + la_row + rr * 64;      // global bs row
            int s  = r & 511;
            int sp = s + k3 - 1;
            float4 v = make_float4(0.f, 0.f, 0.f, 0.f);
            if ((unsigned)sp < 512u)
                v = *reinterpret_cast<const float4*>(
                        A + (size_t)(r - s + sp) * D_ + c0 + la_k4);
            int m = la_row + rr * 64;
            As[la_k4 + 0][m] = v.x;
            As[la_k4 + 1][m] = v.y;
            As[la_k4 + 2][m] = v.z;
            As[la_k4 + 3][m] = v.w;
        }
        // ---- load B tile (coalesced)
        #pragma unroll
        for (int rr = 0; rr < 2; ++rr) {
            int kk = lb_kk + rr * 8;
            *reinterpret_cast<float4*>(&Bs[kk][lb_f4]) =
                *reinterpret_cast<const float4*>(
                    Wt + (size_t)(kk0 + kk) * F_ + colBase + lb_f4);
        }
        __syncthreads();

        #pragma unroll
        for (int kk = 0; kk < 16; ++kk) {
            float a[8], b[8];
            #pragma unroll
            for (int i = 0; i < 8; i++) a[i] = As[kk][ty * 8 + i];
            #pragma unroll
            for (int j = 0; j < 8; j++) b[j] = Bs[kk][tx * 8 + j];
            #pragma unroll
            for (int i = 0; i < 8; i++)
                #pragma unroll
                for (int j = 0; j < 8; j++)
                    acc[i][j] = fmaf(a[i], b[j], acc[i][j]);
        }
        __syncthreads();
    }

    #pragma unroll
    for (int i = 0; i < 8; i++) {
        size_t r = (size_t)(rowBase + ty * 8 + i);
        #pragma unroll
        for (int j = 0; j < 8; j += 4) {
            int f = colBase + tx * 8 + j;
            float4 v;
            v.x = acc[i][j + 0] + bias[f + 0];
            v.y = acc[i][j + 1] + bias[f + 1];
            v.z = acc[i][j + 2] + bias[f + 2];
            v.w = acc[i][j + 3] + bias[f + 3];
            *reinterpret_cast<float4*>(C + r * F_ + f) = v;
        }
    }
}

// ---------------------------------------------------------------------------
// LayerNorm(F=256) + ReLU, in place. One block (256 threads) per row.
// ---------------------------------------------------------------------------
__device__ __forceinline__ float block_sum_256(float v, float* shm) {
    int lane = threadIdx.x & 31, wp = threadIdx.x >> 5;
    #pragma unroll
    for (int o = 16; o > 0; o >>= 1) v += __shfl_xor_sync(0xffffffffu, v, o);
    if (lane == 0) shm[wp] = v;
    __syncthreads();
    float r = shm[lane & 7];   // 8 warps in a 256-thread block
    #pragma unroll
    for (int o = 4; o > 0; o >>= 1) r += __shfl_xor_sync(0xffffffffu, r, o);
    __syncthreads();           // safe to reuse shm after return
    return r;
}

template<int PH>
__global__ __launch_bounds__(256) void ln_relu_k(const float* __restrict__ g,
                                                 const float* __restrict__ be) {
    float* h = (PH == 0) ? g_h1 : g_h2;
    __shared__ float shm[8];
    size_t row = blockIdx.x;
    int tid = threadIdx.x;
    float v  = h[row * F_ + tid];
    float mu = block_sum_256(v, shm) * (1.f / 256.f);
    float d  = v - mu;
    float var = block_sum_256(d * d, shm) * (1.f / 256.f);
    float o = fmaxf(0.f, d * rsqrtf(var + 1e-5f) * g[tid] + be[tid]);
    h[row * F_ + tid] = o;
}

// ---------------------------------------------------------------------------
// Linear head: pred[bs] = relu(h2[bs,:] . lw + lb). One warp per row.
// ---------------------------------------------------------------------------
__global__ __launch_bounds__(256) void linear_k(const float* __restrict__ lw,
                                                const float* __restrict__ lb,
                                                float* __restrict__ pred) {
    int row  = blockIdx.x * 8 + (threadIdx.x >> 5);
    int lane = threadIdx.x & 31;
    const float* h = g_h2 + (size_t)row * F_;
    float s = 0.f;
    #pragma unroll
    for (int i = 0; i < 8; i++) s = fmaf(h[lane + i * 32], lw[lane + i * 32], s);
    #pragma unroll
    for (int o = 16; o > 0; o >>= 1) s += __shfl_xor_sync(0xffffffffu, s, o);
    if (lane == 0) pred[row] = fmaxf(0.f, s + lb[0]);
}

// ---------------------------------------------------------------------------
// Row map: per batch, d = rint(target); cumsum; rowmap[b*L + l] = s for
// l in [start, end), else -1. One block of 512 threads per batch.
// ---------------------------------------------------------------------------
__global__ __launch_bounds__(512) void rowmap_k(const float* __restrict__ target, int L) {
    int b = blockIdx.x, s = threadIdx.x;
    int lane = s & 31, wp = s >> 5;
    int d = (int)rintf(target[b * 512 + s]);   // round-half-even == jnp.round
    int v = d;
    #pragma unroll
    for (int o = 1; o < 32; o <<= 1) {
        int t = __shfl_up_sync(0xffffffffu, v, o);
        if (lane >= o) v += t;
    }
    __shared__ int wsum[16];
    if (lane == 31) wsum[wp] = v;
    __syncthreads();
    if (s < 16) {
        int w = wsum[s];
        #pragma unroll
        for (int o = 1; o < 16; o <<= 1) {
            int t = __shfl_up_sync(0x0000ffffu, w, o);
            if (s >= o) w += t;
        }
        wsum[s] = w;
    }
    __syncthreads();
    int end   = v + (wp ? wsum[wp - 1] : 0);
    int start = end - d;
    int* rm = g_rowmap + (size_t)b * L;
    for (int l = s; l < L; l += 512) rm[l] = -1;
    __syncthreads();
    if (start < L) {
        int e = min(end, L);
        for (int l = start; l < e; ++l) rm[l] = s;
    }
}

// ---------------------------------------------------------------------------
// Gather/expand: out[b, l, :] = (s>=0) ? x[b, s, :] : 0. 4 rows per block.
// ---------------------------------------------------------------------------
__global__ __launch_bounds__(256) void gather_k(const float* __restrict__ x,
                                                float* __restrict__ out, int L) {
    int rowId = blockIdx.x * 4 + (threadIdx.x >> 6);   // rowId == b*L + l
    if (rowId >= B_ * L) return;
    int t = threadIdx.x & 63;
    int b = rowId / L;
    int s = g_rowmap[rowId];
    float4 v = make_float4(0.f, 0.f, 0.f, 0.f);
    if (s >= 0)
        v = *reinterpret_cast<const float4*>(
                x + (size_t)((b << 9) + s) * D_ + (t << 2));
    *reinterpret_cast<float4*>(out + (size_t)rowId * D_ + (t << 2)) = v;
}

// ---------------------------------------------------------------------------
extern "C" void kernel_launch(void* const* d_in, const int* in_sizes, int n_in,
                              void* d_out, int out_size) {
    const float* x   = (const float*)d_in[0];
    const float* tgt = (const float*)d_in[1];
    const float* c1w = (const float*)d_in[2];
    const float* c1b = (const float*)d_in[3];
    const float* c2w = (const float*)d_in[4];
    const float* c2b = (const float*)d_in[5];
    const float* n1g = (const float*)d_in[6];
    const float* n1b = (const float*)d_in[7];
    const float* n2g = (const float*)d_in[8];
    const float* n2b = (const float*)d_in[9];
    const float* lw  = (const float*)d_in[10];
    const float* lb  = (const float*)d_in[11];

    float* out = (float*)d_out;
    // out = concat( expanded [B, L, D], predicted_len [B, S] )
    int L = (out_size - B_ * S_) / (B_ * D_);
    float* pred = out + (size_t)B_ * L * D_;

    transpose_w_k<0><<<(KK_ * F_ + 255) / 256, 256>>>(c1w);
    transpose_w_k<1><<<(KK_ * F_ + 255) / 256, 256>>>(c2w);

    conv_gemm_k<0><<<dim3(BS_ / 128, F_ / 128), 256>>>(x, c1b);
    ln_relu_k<0><<<BS_, 256>>>(n1g, n1b);
    conv_gemm_k<1><<<dim3(BS_ / 128, F_ / 128), 256>>>(x, c2b);
    ln_relu_k<1><<<BS_, 256>>>(n2g, n2b);
    linear_k<<<BS_ / 8, 256>>>(lw, lb, pred);

    rowmap_k<<<B_, 512>>>(tgt, L);
    gather_k<<<(B_ * L + 3) / 4, 256>>>(x, out, L);
}

// round 4
// speedup vs baseline: 2.2604x; 2.2601x over previous
#include <cuda_runtime.h>
#include <cuda_bf16.h>
#include <cstdint>

#define B_  32
#define S_  512
#define D_  256
#define F_  256
#define BS_ 16384
#define KK_ 768
#define NCH 24                 // 768 / 32
#define A_PITCH 80             // 32 bf16 (64B) + 16B pad; 16B-aligned, bank-clean
#define A_TILE (128*A_PITCH)   // 10240
#define W_TILE (256*A_PITCH)   // 20480
#define STG (2*A_TILE + 2*W_TILE)   // 61440
#define OFF_PAR (2*STG)             // 122880
#define OFF_SUM (OFF_PAR + 4096)
#define OFF_SQ  (OFF_SUM + 2048)
#define OFF_LIN (OFF_SQ  + 2048)
#define SMEM_TOTAL (OFF_LIN + 2048) // 133120

__device__ __nv_bfloat16 g_xhi[BS_*D_],  g_xlo[BS_*D_];
__device__ __nv_bfloat16 g_h1hi[BS_*F_], g_h1lo[BS_*F_];
__device__ __nv_bfloat16 g_w1hi[F_*KK_], g_w1lo[F_*KK_];
__device__ __nv_bfloat16 g_w2hi[F_*KK_], g_w2lo[F_*KK_];
__device__ int g_rowmap[B_*4608];

__device__ __forceinline__ uint32_t smem_u32(const void* p) {
    uint32_t a;
    asm("{ .reg .u64 t; cvta.to.shared.u64 t, %1; cvt.u32.u64 %0, t; }" : "=r"(a) : "l"(p));
    return a;
}
__device__ __forceinline__ void cp16(uint32_t dst, const void* src, bool v) {
    int sz = v ? 16 : 0;
    asm volatile("cp.async.cg.shared.global [%0], [%1], 16, %2;" :: "r"(dst), "l"(src), "r"(sz) : "memory");
}
__device__ __forceinline__ void cp_commit() { asm volatile("cp.async.commit_group;" ::: "memory"); }
__device__ __forceinline__ void cp_wait1()  { asm volatile("cp.async.wait_group 1;" ::: "memory"); }
__device__ __forceinline__ void cp_wait0()  { asm volatile("cp.async.wait_group 0;" ::: "memory"); }

__device__ __forceinline__ void ldsm_x4(uint32_t* r, uint32_t a) {
    asm volatile("ldmatrix.sync.aligned.m8n8.x4.shared.b16 {%0,%1,%2,%3}, [%4];"
        : "=r"(r[0]), "=r"(r[1]), "=r"(r[2]), "=r"(r[3]) : "r"(a));
}
__device__ __forceinline__ void ldsm_x2(uint32_t* r, uint32_t a) {
    asm volatile("ldmatrix.sync.aligned.m8n8.x2.shared.b16 {%0,%1}, [%2];"
        : "=r"(r[0]), "=r"(r[1]) : "r"(a));
}
__device__ __forceinline__ void mma16816(float* d, const uint32_t* a, const uint32_t* b) {
    asm volatile("mma.sync.aligned.m16n8k16.row.col.f32.bf16.bf16.f32 "
        "{%0,%1,%2,%3}, {%4,%5,%6,%7}, {%8,%9}, {%0,%1,%2,%3};"
        : "+f"(d[0]), "+f"(d[1]), "+f"(d[2]), "+f"(d[3])
        : "r"(a[0]), "r"(a[1]), "r"(a[2]), "r"(a[3]), "r"(b[0]), "r"(b[1]));
}

// ---- prep ----
__global__ __launch_bounds__(256) void cvt_x_k(const float* __restrict__ x) {
    int i = blockIdx.x * 256 + threadIdx.x;
    float4 v = reinterpret_cast<const float4*>(x)[i];
    __nv_bfloat162 h01 = __floats2bfloat162_rn(v.x, v.y);
    __nv_bfloat162 h23 = __floats2bfloat162_rn(v.z, v.w);
    __nv_bfloat162 l01 = __floats2bfloat162_rn(v.x - __bfloat162float(h01.x), v.y - __bfloat162float(h01.y));
    __nv_bfloat162 l23 = __floats2bfloat162_rn(v.z - __bfloat162float(h23.x), v.w - __bfloat162float(h23.y));
    reinterpret_cast<uint2*>(g_xhi)[i] = make_uint2(*(uint32_t*)&h01, *(uint32_t*)&h23);
    reinterpret_cast<uint2*>(g_xlo)[i] = make_uint2(*(uint32_t*)&l01, *(uint32_t*)&l23);
}
template<int PH>
__global__ __launch_bounds__(256) void cvt_w_k(const float* __restrict__ w) {
    int idx = blockIdx.x * 256 + threadIdx.x;   // dest [f][tap*256+c]
    int f = idx / 768, rem = idx - f * 768;
    int k = rem >> 8, c = rem & 255;
    float v = w[f * 768 + c * 3 + k];
    __nv_bfloat16 h = __float2bfloat16(v);
    (PH ? g_w2hi : g_w1hi)[idx] = h;
    (PH ? g_w2lo : g_w1lo)[idx] = __float2bfloat16(v - __bfloat162float(h));
}

__device__ __forceinline__ void load_chunk(
    uint32_t stg, int chunk,
    const __nv_bfloat16* __restrict__ Ahi, const __nv_bfloat16* __restrict__ Alo,
    const __nv_bfloat16* __restrict__ Whi, const __nv_bfloat16* __restrict__ Wlo,
    int mBase, int tid)
{
    const int tap = chunk >> 3, c0 = (chunk & 7) << 5;
    #pragma unroll
    for (int v = 0; v < 4; v++) {                 // A: 1024 cp16 (hi+lo)
        int id  = (v << 8) + tid;
        int idx = id & 511, row = idx >> 2, seg = idx & 3;
        const __nv_bfloat16* src = (id < 512) ? Ahi : Alo;
        int rG = mBase + row, s = rG & 511, sp = s + tap - 1;
        bool val = ((unsigned)sp < 512u);
        size_t go = val ? (((size_t)(rG - s + sp)) << 8) + c0 + (seg << 3) : 0;
        cp16(stg + (id >> 9) * A_TILE + row * A_PITCH + (seg << 4), src + go, val);
    }
    #pragma unroll
    for (int v = 0; v < 8; v++) {                 // W: 2048 cp16 (hi+lo)
        int id  = (v << 8) + tid;
        int idx = id & 1023, row = idx >> 2, seg = idx & 3;
        const __nv_bfloat16* src = (id < 1024) ? Whi : Wlo;
        cp16(stg + 2 * A_TILE + (id >> 10) * W_TILE + row * A_PITCH + (seg << 4),
             src + (size_t)row * 768 + (chunk << 5) + (seg << 3), true);
    }
}

// ---- fused conv GEMM (HMMA) + bias + LN + ReLU (+ linear head) ----
template<int PH>
__global__ __launch_bounds__(256) void conv_mma_k(
    const float* __restrict__ bias, const float* __restrict__ gam,
    const float* __restrict__ bet, const float* __restrict__ lw,
    const float* __restrict__ lbp, float* __restrict__ pred)
{
    extern __shared__ char smem[];
    const uint32_t sb = smem_u32(smem);
    float* sPar = (float*)(smem + OFF_PAR);
    float* sSum = (float*)(smem + OFF_SUM);
    float* sSq  = (float*)(smem + OFF_SQ);
    float* sLin = (float*)(smem + OFF_LIN);
    const int tid = threadIdx.x, lane = tid & 31, warp = tid >> 5;
    const int mw = warp >> 2, nw = warp & 3;
    const int mBase = blockIdx.x * 128;

    const __nv_bfloat16* Ahi = PH ? g_h1hi : g_xhi;
    const __nv_bfloat16* Alo = PH ? g_h1lo : g_xlo;
    const __nv_bfloat16* Whi = PH ? g_w2hi : g_w1hi;
    const __nv_bfloat16* Wlo = PH ? g_w2lo : g_w1lo;

    sPar[tid] = bias[tid]; sPar[256 + tid] = gam[tid];
    sPar[512 + tid] = bet[tid]; sPar[768 + tid] = PH ? lw[tid] : 0.f;

    float acc[4][8][4];
    #pragma unroll
    for (int a = 0; a < 4; a++)
        #pragma unroll
        for (int b = 0; b < 8; b++)
            #pragma unroll
            for (int c = 0; c < 4; c++) acc[a][b][c] = 0.f;

    load_chunk(sb, 0, Ahi, Alo, Whi, Wlo, mBase, tid);
    cp_commit();

    for (int i = 0; i < NCH; i++) {
        if (i + 1 < NCH) {
            load_chunk(sb + ((i + 1) & 1) * STG, i + 1, Ahi, Alo, Whi, Wlo, mBase, tid);
            cp_commit();
            cp_wait1();
        } else {
            cp_wait0();
        }
        __syncthreads();
        const uint32_t st  = sb + (i & 1) * STG;
        const uint32_t aHi = st, aLo = st + A_TILE;
        const uint32_t wHi = st + 2 * A_TILE, wLo = wHi + W_TILE;
        #pragma unroll
        for (int ks = 0; ks < 2; ks++) {
            const int kb = ks * 32;          // byte offset of k0 within row
            uint32_t bh[8][2], bl[8][2];
            #pragma unroll
            for (int nj = 0; nj < 8; nj++) {
                uint32_t ad = (uint32_t)(nw * 64 + nj * 8 + (lane & 7)) * A_PITCH
                              + kb + ((lane >> 3) & 1) * 16;
                ldsm_x2(bh[nj], wHi + ad);
                ldsm_x2(bl[nj], wLo + ad);
            }
            #pragma unroll
            for (int mi = 0; mi < 4; mi++) {
                uint32_t ad = (uint32_t)(mw * 64 + mi * 16 + (lane & 7) + ((lane >> 3) & 1) * 8) * A_PITCH
                              + kb + ((lane >> 4) & 1) * 16;
                uint32_t ah[4], al[4];
                ldsm_x4(ah, aHi + ad);
                ldsm_x4(al, aLo + ad);
                #pragma unroll
                for (int nj = 0; nj < 8; nj++) {
                    mma16816(acc[mi][nj], ah, bh[nj]);
                    mma16816(acc[mi][nj], ah, bl[nj]);
                    mma16816(acc[mi][nj], al, bh[nj]);
                }
            }
        }
        __syncthreads();
    }

    // ---- epilogue: bias + LN partials ----
    #pragma unroll
    for (int mi = 0; mi < 4; mi++)
        #pragma unroll
        for (int rh = 0; rh < 2; rh++) {
            float s = 0.f, q = 0.f;
            #pragma unroll
            for (int nj = 0; nj < 8; nj++)
                #pragma unroll
                for (int h = 0; h < 2; h++) {
                    int col = nw * 64 + nj * 8 + 2 * (lane & 3) + h;
                    float v = acc[mi][nj][rh * 2 + h] + sPar[col];
                    acc[mi][nj][rh * 2 + h] = v;
                    s += v; q = fmaf(v, v, q);
                }
            s += __shfl_xor_sync(0xffffffffu, s, 1); s += __shfl_xor_sync(0xffffffffu, s, 2);
            q += __shfl_xor_sync(0xffffffffu, q, 1); q += __shfl_xor_sync(0xffffffffu, q, 2);
            if ((lane & 3) == 0) {
                int r = mw * 64 + mi * 16 + rh * 8 + (lane >> 2);
                sSum[nw * 128 + r] = s; sSq[nw * 128 + r] = q;
            }
        }
    __syncthreads();

    float lacc[4][2];
    #pragma unroll
    for (int mi = 0; mi < 4; mi++)
        #pragma unroll
        for (int rh = 0; rh < 2; rh++) {
            int r = mw * 64 + mi * 16 + rh * 8 + (lane >> 2);
            float tot = sSum[r] + sSum[128 + r] + sSum[256 + r] + sSum[384 + r];
            float tq  = sSq[r]  + sSq[128 + r]  + sSq[256 + r]  + sSq[384 + r];
            float mu = tot * (1.f / 256.f);
            float rstd = rsqrtf(tq * (1.f / 256.f) - mu * mu + 1e-5f);
            int rG = mBase + r;
            float la = 0.f;
            #pragma unroll
            for (int nj = 0; nj < 8; nj++) {
                int col0 = nw * 64 + nj * 8 + 2 * (lane & 3);
                float v0 = acc[mi][nj][rh * 2 + 0], v1 = acc[mi][nj][rh * 2 + 1];
                float o0 = fmaxf(0.f, fmaf((v0 - mu) * rstd, sPar[256 + col0],     sPar[512 + col0]));
                float o1 = fmaxf(0.f, fmaf((v1 - mu) * rstd, sPar[256 + col0 + 1], sPar[512 + col0 + 1]));
                if (PH == 0) {
                    __nv_bfloat162 hx = __floats2bfloat162_rn(o0, o1);
                    __nv_bfloat162 lx = __floats2bfloat162_rn(o0 - __bfloat162float(hx.x),
                                                              o1 - __bfloat162float(hx.y));
                    *(uint32_t*)(g_h1hi + (size_t)rG * 256 + col0) = *(uint32_t*)&hx;
                    *(uint32_t*)(g_h1lo + (size_t)rG * 256 + col0) = *(uint32_t*)&lx;
                } else {
                    la = fmaf(o0, sPar[768 + col0], la);
                    la = fmaf(o1, sPar[768 + col0 + 1], la);
                }
            }
            lacc[mi][rh] = la;
        }

    if (PH == 1) {
        #pragma unroll
        for (int mi = 0; mi < 4; mi++)
            #pragma unroll
            for (int rh = 0; rh < 2; rh++) {
                float la = lacc[mi][rh];
                la += __shfl_xor_sync(0xffffffffu, la, 1);
                la += __shfl_xor_sync(0xffffffffu, la, 2);
                if ((lane & 3) == 0)
                    sLin[nw * 128 + mw * 64 + mi * 16 + rh * 8 + (lane >> 2)] = la;
            }
        __syncthreads();
        if (nw == 0 && (lane & 3) == 0) {
            #pragma unroll
            for (int mi = 0; mi < 4; mi++)
                #pragma unroll
                for (int rh = 0; rh < 2; rh++) {
                    int r = mw * 64 + mi * 16 + rh * 8 + (lane >> 2);
                    float t = sLin[r] + sLin[128 + r] + sLin[256 + r] + sLin[384 + r];
                    pred[mBase + r] = fmaxf(0.f, t + lbp[0]);
                }
        }
    }
}

// ---- rowmap + gather (unchanged, proven) ----
__global__ __launch_bounds__(512) void rowmap_k(const float* __restrict__ target, int L) {
    int b = blockIdx.x, s = threadIdx.x;
    int lane = s & 31, wp = s >> 5;
    int d = (int)rintf(target[b * 512 + s]);
    int v = d;
    #pragma unroll
    for (int o = 1; o < 32; o <<= 1) {
        int t = __shfl_up_sync(0xffffffffu, v, o);
        if (lane >= o) v += t;
    }
    __shared__ int wsum[16];
    if (lane == 31) wsum[wp] = v;
    __syncthreads();
    if (s < 16) {
        int w = wsum[s];
        #pragma unroll
        for (int o = 1; o < 16; o <<= 1) {
            int t = __shfl_up_sync(0x0000ffffu, w, o);
            if (s >= o) w += t;
        }
        wsum[s] = w;
    }
    __syncthreads();
    int end = v + (wp ? wsum[wp - 1] : 0);
    int start = end - d;
    int* rm = g_rowmap + (size_t)b * L;
    for (int l = s; l < L; l += 512) rm[l] = -1;
    __syncthreads();
    if (start < L) {
        int e = min(end, L);
        for (int l = start; l < e; ++l) rm[l] = s;
    }
}

__global__ __launch_bounds__(256) void gather_k(const float* __restrict__ x,
                                                float* __restrict__ out, int L) {
    int rowId = blockIdx.x * 4 + (threadIdx.x >> 6);
    if (rowId >= B_ * L) return;
    int t = threadIdx.x & 63;
    int b = rowId / L;
    int s = g_rowmap[rowId];
    float4 v = make_float4(0.f, 0.f, 0.f, 0.f);
    if (s >= 0)
        v = *reinterpret_cast<const float4*>(x + (size_t)((b << 9) + s) * D_ + (t << 2));
    *reinterpret_cast<float4*>(out + (size_t)rowId * D_ + (t << 2)) = v;
}

extern "C" void kernel_launch(void* const* d_in, const int* in_sizes, int n_in,
                              void* d_out, int out_size) {
    const float* x   = (const float*)d_in[0];
    const float* tgt = (const float*)d_in[1];
    const float* c1w = (const float*)d_in[2];
    const float* c1b = (const float*)d_in[3];
    const float* c2w = (const float*)d_in[4];
    const float* c2b = (const float*)d_in[5];
    const float* n1g = (const float*)d_in[6];
    const float* n1b = (const float*)d_in[7];
    const float* n2g = (const float*)d_in[8];
    const float* n2b = (const float*)d_in[9];
    const float* lw  = (const float*)d_in[10];
    const float* lb  = (const float*)d_in[11];

    float* out = (float*)d_out;
    int L = (out_size - B_ * S_) / (B_ * D_);
    float* pred = out + (size_t)B_ * L * D_;

    cudaFuncSetAttribute(conv_mma_k<0>, cudaFuncAttributeMaxDynamicSharedMemorySize, SMEM_TOTAL);
    cudaFuncSetAttribute(conv_mma_k<1>, cudaFuncAttributeMaxDynamicSharedMemorySize, SMEM_TOTAL);

    cvt_x_k<<<BS_ * D_ / 4 / 256, 256>>>(x);
    cvt_w_k<0><<<F_ * KK_ / 256, 256>>>(c1w);
    cvt_w_k<1><<<F_ * KK_ / 256, 256>>>(c2w);

    conv_mma_k<0><<<128, 256, SMEM_TOTAL>>>(c1b, n1g, n1b, lw, lb, pred);
    conv_mma_k<1><<<128, 256, SMEM_TOTAL>>>(c2b, n2g, n2b, lw, lb, pred);

    rowmap_k<<<B_, 512>>>(tgt, L);
    gather_k<<<(B_ * L + 3) / 4, 256>>>(x, out, L);
}

// round 5
// speedup vs baseline: 4.2940x; 1.8996x over previous
#include <cuda_runtime.h>
#include <cuda_fp16.h>
#include <cstdint>

#define B_  32
#define S_  512
#define D_  256
#define F_  256
#define BS_ 16384
#define KK_ 768
#define NCH 12                  // 768 / 64
#define PITCH 144               // 64 fp16 (128B) + 16B pad; 9x16B (odd) -> ldmatrix clean
#define A_TILE (128*PITCH)      // 18432
#define W_TILE (256*PITCH)      // 36864
#define STG (A_TILE + W_TILE)   // 55296
#define OFF_PAR (2*STG)         // 110592
#define OFF_SUM (OFF_PAR + 4096)
#define OFF_SQ  (OFF_SUM + 2048)
#define OFF_LIN (OFF_SQ  + 2048)
#define SMEM_TOTAL (OFF_LIN + 2048)   // 120832

__device__ __half g_xh[BS_*D_];
__device__ __half g_h1h[BS_*F_];
__device__ __half g_w1h[F_*KK_];
__device__ __half g_w2h[F_*KK_];
__device__ int g_rowmap[B_*4608];

__device__ __forceinline__ uint32_t smem_u32(const void* p) {
    uint32_t a;
    asm("{ .reg .u64 t; cvta.to.shared.u64 t, %1; cvt.u32.u64 %0, t; }" : "=r"(a) : "l"(p));
    return a;
}
__device__ __forceinline__ void cp16(uint32_t dst, const void* src, bool v) {
    int sz = v ? 16 : 0;
    asm volatile("cp.async.cg.shared.global [%0], [%1], 16, %2;" :: "r"(dst), "l"(src), "r"(sz) : "memory");
}
__device__ __forceinline__ void cp_commit() { asm volatile("cp.async.commit_group;" ::: "memory"); }
__device__ __forceinline__ void cp_wait1()  { asm volatile("cp.async.wait_group 1;" ::: "memory"); }
__device__ __forceinline__ void cp_wait0()  { asm volatile("cp.async.wait_group 0;" ::: "memory"); }

__device__ __forceinline__ void ldsm_x4(uint32_t* r, uint32_t a) {
    asm volatile("ldmatrix.sync.aligned.m8n8.x4.shared.b16 {%0,%1,%2,%3}, [%4];"
        : "=r"(r[0]), "=r"(r[1]), "=r"(r[2]), "=r"(r[3]) : "r"(a));
}
__device__ __forceinline__ void ldsm_x2(uint32_t* r, uint32_t a) {
    asm volatile("ldmatrix.sync.aligned.m8n8.x2.shared.b16 {%0,%1}, [%2];"
        : "=r"(r[0]), "=r"(r[1]) : "r"(a));
}
__device__ __forceinline__ void mma_f16(float* d, const uint32_t* a, const uint32_t* b) {
    asm volatile("mma.sync.aligned.m16n8k16.row.col.f32.f16.f16.f32 "
        "{%0,%1,%2,%3}, {%4,%5,%6,%7}, {%8,%9}, {%0,%1,%2,%3};"
        : "+f"(d[0]), "+f"(d[1]), "+f"(d[2]), "+f"(d[3])
        : "r"(a[0]), "r"(a[1]), "r"(a[2]), "r"(a[3]), "r"(b[0]), "r"(b[1]));
}

// ---- prep ----
__global__ __launch_bounds__(256) void cvt_x_k(const float* __restrict__ x) {
    int i = blockIdx.x * 256 + threadIdx.x;
    float4 v = reinterpret_cast<const float4*>(x)[i];
    __half2 h01 = __floats2half2_rn(v.x, v.y);
    __half2 h23 = __floats2half2_rn(v.z, v.w);
    reinterpret_cast<uint2*>(g_xh)[i] = make_uint2(*(uint32_t*)&h01, *(uint32_t*)&h23);
}
template<int PH>
__global__ __launch_bounds__(256) void cvt_w_k(const float* __restrict__ w) {
    int idx = blockIdx.x * 256 + threadIdx.x;   // dest [f][tap*256+c]
    int f = idx / 768, rem = idx - f * 768;
    int k = rem >> 8, c = rem & 255;
    (PH ? g_w2h : g_w1h)[idx] = __float2half(w[f * 768 + c * 3 + k]);
}

__device__ __forceinline__ void load_chunk(
    uint32_t stg, int chunk,
    const __half* __restrict__ A, const __half* __restrict__ W,
    int mBase, int tid)
{
    const int tap = chunk >> 2, c0 = (chunk & 3) << 6;
    #pragma unroll
    for (int v = 0; v < 4; v++) {               // A: 1024 cp16 (128 rows x 128B)
        int id = (v << 8) + tid;
        int row = id >> 3, seg = id & 7;
        int rG = mBase + row, s = rG & 511, sp = s + tap - 1;
        bool val = ((unsigned)sp < 512u);
        size_t go = val ? (((size_t)(rG - s + sp)) << 8) + c0 + (seg << 3) : 0;
        cp16(stg + row * PITCH + (seg << 4), A + go, val);
    }
    #pragma unroll
    for (int v = 0; v < 8; v++) {               // W: 2048 cp16 (256 rows x 128B)
        int id = (v << 8) + tid;
        int row = id >> 3, seg = id & 7;
        cp16(stg + A_TILE + row * PITCH + (seg << 4),
             W + (size_t)row * 768 + (chunk << 6) + (seg << 3), true);
    }
}

// ---- fused conv GEMM (fp16 HMMA) + bias + LN + ReLU (+ linear head) ----
template<int PH>
__global__ __launch_bounds__(256) void conv_mma_k(
    const float* __restrict__ bias, const float* __restrict__ gam,
    const float* __restrict__ bet, const float* __restrict__ lw,
    const float* __restrict__ lbp, float* __restrict__ pred)
{
    extern __shared__ char smem[];
    const uint32_t sb = smem_u32(smem);
    float* sPar = (float*)(smem + OFF_PAR);
    float* sSum = (float*)(smem + OFF_SUM);
    float* sSq  = (float*)(smem + OFF_SQ);
    float* sLin = (float*)(smem + OFF_LIN);
    const int tid = threadIdx.x, lane = tid & 31, warp = tid >> 5;
    const int mw = warp >> 2, nw = warp & 3;
    const int mBase = blockIdx.x * 128;

    const __half* A = PH ? g_h1h : g_xh;
    const __half* W = PH ? g_w2h : g_w1h;

    sPar[tid] = bias[tid]; sPar[256 + tid] = gam[tid];
    sPar[512 + tid] = bet[tid]; sPar[768 + tid] = PH ? lw[tid] : 0.f;

    float acc[4][8][4];
    #pragma unroll
    for (int a = 0; a < 4; a++)
        #pragma unroll
        for (int b = 0; b < 8; b++)
            #pragma unroll
            for (int c = 0; c < 4; c++) acc[a][b][c] = 0.f;

    load_chunk(sb, 0, A, W, mBase, tid);
    cp_commit();

    for (int i = 0; i < NCH; i++) {
        if (i + 1 < NCH) {
            load_chunk(sb + ((i + 1) & 1) * STG, i + 1, A, W, mBase, tid);
            cp_commit();
            cp_wait1();
        } else {
            cp_wait0();
        }
        __syncthreads();
        const uint32_t st = sb + (i & 1) * STG;
        const uint32_t aT = st, wT = st + A_TILE;
        #pragma unroll
        for (int ks = 0; ks < 4; ks++) {
            const int kb = ks * 32;
            uint32_t bf[8][2];
            #pragma unroll
            for (int nj = 0; nj < 8; nj++) {
                uint32_t ad = (uint32_t)(nw * 64 + nj * 8 + (lane & 7)) * PITCH
                              + kb + ((lane >> 3) & 1) * 16;
                ldsm_x2(bf[nj], wT + ad);
            }
            #pragma unroll
            for (int mi = 0; mi < 4; mi++) {
                uint32_t ad = (uint32_t)(mw * 64 + mi * 16 + (lane & 7) + ((lane >> 3) & 1) * 8) * PITCH
                              + kb + ((lane >> 4) & 1) * 16;
                uint32_t af[4];
                ldsm_x4(af, aT + ad);
                #pragma unroll
                for (int nj = 0; nj < 8; nj++)
                    mma_f16(acc[mi][nj], af, bf[nj]);
            }
        }
        __syncthreads();
    }

    // ---- epilogue: bias + LN partials ----
    #pragma unroll
    for (int mi = 0; mi < 4; mi++)
        #pragma unroll
        for (int rh = 0; rh < 2; rh++) {
            float s = 0.f, q = 0.f;
            #pragma unroll
            for (int nj = 0; nj < 8; nj++)
                #pragma unroll
                for (int h = 0; h < 2; h++) {
                    int col = nw * 64 + nj * 8 + 2 * (lane & 3) + h;
                    float v = acc[mi][nj][rh * 2 + h] + sPar[col];
                    acc[mi][nj][rh * 2 + h] = v;
                    s += v; q = fmaf(v, v, q);
                }
            s += __shfl_xor_sync(0xffffffffu, s, 1); s += __shfl_xor_sync(0xffffffffu, s, 2);
            q += __shfl_xor_sync(0xffffffffu, q, 1); q += __shfl_xor_sync(0xffffffffu, q, 2);
            if ((lane & 3) == 0) {
                int r = mw * 64 + mi * 16 + rh * 8 + (lane >> 2);
                sSum[nw * 128 + r] = s; sSq[nw * 128 + r] = q;
            }
        }
    __syncthreads();

    float lacc[4][2];
    #pragma unroll
    for (int mi = 0; mi < 4; mi++)
        #pragma unroll
        for (int rh = 0; rh < 2; rh++) {
            int r = mw * 64 + mi * 16 + rh * 8 + (lane >> 2);
            float tot = sSum[r] + sSum[128 + r] + sSum[256 + r] + sSum[384 + r];
            float tq  = sSq[r]  + sSq[128 + r]  + sSq[256 + r]  + sSq[384 + r];
            float mu = tot * (1.f / 256.f);
            float rstd = rsqrtf(tq * (1.f / 256.f) - mu * mu + 1e-5f);
            int rG = mBase + r;
            float la = 0.f;
            #pragma unroll
            for (int nj = 0; nj < 8; nj++) {
                int col0 = nw * 64 + nj * 8 + 2 * (lane & 3);
                float v0 = acc[mi][nj][rh * 2 + 0], v1 = acc[mi][nj][rh * 2 + 1];
                float o0 = fmaxf(0.f, fmaf((v0 - mu) * rstd, sPar[256 + col0],     sPar[512 + col0]));
                float o1 = fmaxf(0.f, fmaf((v1 - mu) * rstd, sPar[256 + col0 + 1], sPar[512 + col0 + 1]));
                if (PH == 0) {
                    __half2 hx = __floats2half2_rn(o0, o1);
                    *(uint32_t*)(g_h1h + (size_t)rG * 256 + col0) = *(uint32_t*)&hx;
                } else {
                    la = fmaf(o0, sPar[768 + col0], la);
                    la = fmaf(o1, sPar[768 + col0 + 1], la);
                }
            }
            lacc[mi][rh] = la;
        }

    if (PH == 1) {
        #pragma unroll
        for (int mi = 0; mi < 4; mi++)
            #pragma unroll
            for (int rh = 0; rh < 2; rh++) {
                float la = lacc[mi][rh];
                la += __shfl_xor_sync(0xffffffffu, la, 1);
                la += __shfl_xor_sync(0xffffffffu, la, 2);
                if ((lane & 3) == 0)
                    sLin[nw * 128 + mw * 64 + mi * 16 + rh * 8 + (lane >> 2)] = la;
            }
        __syncthreads();
        if (nw == 0 && (lane & 3) == 0) {
            #pragma unroll
            for (int mi = 0; mi < 4; mi++)
                #pragma unroll
                for (int rh = 0; rh < 2; rh++) {
                    int r = mw * 64 + mi * 16 + rh * 8 + (lane >> 2);
                    float t = sLin[r] + sLin[128 + r] + sLin[256 + r] + sLin[384 + r];
                    pred[mBase + r] = fmaxf(0.f, t + lbp[0]);
                }
        }
    }
}

// ---- rowmap + gather (unchanged, proven) ----
__global__ __launch_bounds__(512) void rowmap_k(const float* __restrict__ target, int L) {
    int b = blockIdx.x, s = threadIdx.x;
    int lane = s & 31, wp = s >> 5;
    int d = (int)rintf(target[b * 512 + s]);
    int v = d;
    #pragma unroll
    for (int o = 1; o < 32; o <<= 1) {
        int t = __shfl_up_sync(0xffffffffu, v, o);
        if (lane >= o) v += t;
    }
    __shared__ int wsum[16];
    if (lane == 31) wsum[wp] = v;
    __syncthreads();
    if (s < 16) {
        int w = wsum[s];
        #pragma unroll
        for (int o = 1; o < 16; o <<= 1) {
            int t = __shfl_up_sync(0x0000ffffu, w, o);
            if (s >= o) w += t;
        }
        wsum[s] = w;
    }
    __syncthreads();
    int end = v + (wp ? wsum[wp - 1] : 0);
    int start = end - d;
    int* rm = g_rowmap + (size_t)b * L;
    for (int l = s; l < L; l += 512) rm[l] = -1;
    __syncthreads();
    if (start < L) {
        int e = min(end, L);
        for (int l = start; l < e; ++l) rm[l] = s;
    }
}

__global__ __launch_bounds__(256) void gather_k(const float* __restrict__ x,
                                                float* __restrict__ out, int L) {
    int rowId = blockIdx.x * 4 + (threadIdx.x >> 6);
    if (rowId >= B_ * L) return;
    int t = threadIdx.x & 63;
    int b = rowId / L;
    int s = g_rowmap[rowId];
    float4 v = make_float4(0.f, 0.f, 0.f, 0.f);
    if (s >= 0)
        v = *reinterpret_cast<const float4*>(x + (size_t)((b << 9) + s) * D_ + (t << 2));
    *reinterpret_cast<float4*>(out + (size_t)rowId * D_ + (t << 2)) = v;
}

extern "C" void kernel_launch(void* const* d_in, const int* in_sizes, int n_in,
                              void* d_out, int out_size) {
    const float* x   = (const float*)d_in[0];
    const float* tgt = (const float*)d_in[1];
    const float* c1w = (const float*)d_in[2];
    const float* c1b = (const float*)d_in[3];
    const float* c2w = (const float*)d_in[4];
    const float* c2b = (const float*)d_in[5];
    const float* n1g = (const float*)d_in[6];
    const float* n1b = (const float*)d_in[7];
    const float* n2g = (const float*)d_in[8];
    const float* n2b = (const float*)d_in[9];
    const float* lw  = (const float*)d_in[10];
    const float* lb  = (const float*)d_in[11];

    float* out = (float*)d_out;
    int L = (out_size - B_ * S_) / (B_ * D_);
    float* pred = out + (size_t)B_ * L * D_;

    cudaFuncSetAttribute(conv_mma_k<0>, cudaFuncAttributeMaxDynamicSharedMemorySize, SMEM_TOTAL);
    cudaFuncSetAttribute(conv_mma_k<1>, cudaFuncAttributeMaxDynamicSharedMemorySize, SMEM_TOTAL);

    cvt_x_k<<<BS_ * D_ / 4 / 256, 256>>>(x);
    cvt_w_k<0><<<F_ * KK_ / 256, 256>>>(c1w);
    cvt_w_k<1><<<F_ * KK_ / 256, 256>>>(c2w);

    conv_mma_k<0><<<128, 256, SMEM_TOTAL>>>(c1b, n1g, n1b, lw, lb, pred);
    conv_mma_k<1><<<128, 256, SMEM_TOTAL>>>(c2b, n2g, n2b, lw, lb, pred);

    rowmap_k<<<B_, 512>>>(tgt, L);
    gather_k<<<(B_ * L + 3) / 4, 256>>>(x, out, L);
}

// round 6
// speedup vs baseline: 4.3092x; 1.0035x over previous
#include <cuda_runtime.h>
#include <cuda_fp16.h>
#include <cstdint>

#define B_  32
#define S_  512
#define D_  256
#define F_  256
#define BS_ 16384
#define KK_ 768
#define NCH 12                  // 768 / 64
#define PITCH 144               // 64 fp16 (128B) + 16B pad; odd 16B units -> ldmatrix clean
#define A_TILE (128*PITCH)      // 18432
#define W_TILE (256*PITCH)      // 36864
#define STG (A_TILE + W_TILE)   // 55296
#define OFF_PAR (2*STG)         // 110592
#define OFF_SUM (OFF_PAR + 4096)
#define OFF_SQ  (OFF_SUM + 2048)
#define OFF_LIN (OFF_SQ  + 2048)
#define SMEM_TOTAL (OFF_LIN + 2048)   // 120832

__device__ __half g_xh[BS_*D_];
__device__ __half g_h1h[BS_*F_];
__device__ __half g_w1h[F_*KK_];
__device__ __half g_w2h[F_*KK_];
__device__ int g_rowmap[B_*4608];

__device__ __forceinline__ uint32_t smem_u32(const void* p) {
    uint32_t a;
    asm("{ .reg .u64 t; cvta.to.shared.u64 t, %1; cvt.u32.u64 %0, t; }" : "=r"(a) : "l"(p));
    return a;
}
__device__ __forceinline__ void cp16(uint32_t dst, const void* src, bool v) {
    int sz = v ? 16 : 0;
    asm volatile("cp.async.cg.shared.global [%0], [%1], 16, %2;" :: "r"(dst), "l"(src), "r"(sz) : "memory");
}
__device__ __forceinline__ void cp_commit() { asm volatile("cp.async.commit_group;" ::: "memory"); }
__device__ __forceinline__ void cp_wait1()  { asm volatile("cp.async.wait_group 1;" ::: "memory"); }
__device__ __forceinline__ void cp_wait0()  { asm volatile("cp.async.wait_group 0;" ::: "memory"); }

__device__ __forceinline__ void ldsm_x4(uint32_t* r, uint32_t a) {
    asm volatile("ldmatrix.sync.aligned.m8n8.x4.shared.b16 {%0,%1,%2,%3}, [%4];"
        : "=r"(r[0]), "=r"(r[1]), "=r"(r[2]), "=r"(r[3]) : "r"(a));
}
__device__ __forceinline__ void ldsm_x2(uint32_t* r, uint32_t a) {
    asm volatile("ldmatrix.sync.aligned.m8n8.x2.shared.b16 {%0,%1}, [%2];"
        : "=r"(r[0]), "=r"(r[1]) : "r"(a));
}
__device__ __forceinline__ void mma_f16(float* d, const uint32_t* a, const uint32_t* b) {
    asm volatile("mma.sync.aligned.m16n8k16.row.col.f32.f16.f16.f32 "
        "{%0,%1,%2,%3}, {%4,%5,%6,%7}, {%8,%9}, {%0,%1,%2,%3};"
        : "+f"(d[0]), "+f"(d[1]), "+f"(d[2]), "+f"(d[3])
        : "r"(a[0]), "r"(a[1]), "r"(a[2]), "r"(a[3]), "r"(b[0]), "r"(b[1]));
}

// ---- prep ----
__global__ __launch_bounds__(256) void cvt_x_k(const float* __restrict__ x) {
    int i = blockIdx.x * 256 + threadIdx.x;
    float4 v = reinterpret_cast<const float4*>(x)[i];
    __half2 h01 = __floats2half2_rn(v.x, v.y);
    __half2 h23 = __floats2half2_rn(v.z, v.w);
    reinterpret_cast<uint2*>(g_xh)[i] = make_uint2(*(uint32_t*)&h01, *(uint32_t*)&h23);
}
__global__ __launch_bounds__(256) void cvt_w_k(const float* __restrict__ w1,
                                               const float* __restrict__ w2) {
    int gid = blockIdx.x * 256 + threadIdx.x;
    int ph = gid >= F_ * KK_;
    int idx = ph ? gid - F_ * KK_ : gid;       // dest [f][tap*256+c]
    int f = idx / 768, rem = idx - f * 768;
    int k = rem >> 8, c = rem & 255;
    const float* w = ph ? w2 : w1;
    (ph ? g_w2h : g_w1h)[idx] = __float2half(w[f * 768 + c * 3 + k]);
}

__device__ __forceinline__ void load_chunk(
    uint32_t stg, int chunk,
    const __half* __restrict__ A, const __half* __restrict__ W,
    int mBase, int tid)
{
    const int tap = chunk >> 2, c0 = (chunk & 3) << 6;
    #pragma unroll
    for (int v = 0; v < 2; v++) {               // A: 1024 cp16 (128 rows x 128B)
        int id = (v << 9) + tid;
        int row = id >> 3, seg = id & 7;
        int rG = mBase + row, s = rG & 511, sp = s + tap - 1;
        bool val = ((unsigned)sp < 512u);
        size_t go = val ? (((size_t)(rG - s + sp)) << 8) + c0 + (seg << 3) : 0;
        cp16(stg + row * PITCH + (seg << 4), A + go, val);
    }
    #pragma unroll
    for (int v = 0; v < 4; v++) {               // W: 2048 cp16 (256 rows x 128B)
        int id = (v << 9) + tid;
        int row = id >> 3, seg = id & 7;
        cp16(stg + A_TILE + row * PITCH + (seg << 4),
             W + (size_t)row * 768 + (chunk << 6) + (seg << 3), true);
    }
}

// ---- fused conv GEMM (fp16 HMMA, 16 warps) + bias + LN + ReLU (+ linear head) ----
template<int PH>
__global__ __launch_bounds__(512) void conv_mma_k(
    const float* __restrict__ bias, const float* __restrict__ gam,
    const float* __restrict__ bet, const float* __restrict__ lw,
    const float* __restrict__ lbp, float* __restrict__ pred)
{
    extern __shared__ char smem[];
    const uint32_t sb = smem_u32(smem);
    float* sPar = (float*)(smem + OFF_PAR);
    float* sSum = (float*)(smem + OFF_SUM);
    float* sSq  = (float*)(smem + OFF_SQ);
    float* sLin = (float*)(smem + OFF_LIN);
    const int tid = threadIdx.x, lane = tid & 31, warp = tid >> 5;
    const int mw = warp >> 2, nw = warp & 3;      // 4x4 warp grid, tile 32(M)x64(N)
    const int mBase = blockIdx.x * 128;

    const __half* A = PH ? g_h1h : g_xh;
    const __half* W = PH ? g_w2h : g_w1h;

    if (tid < 256) {
        sPar[tid] = bias[tid]; sPar[256 + tid] = gam[tid];
        sPar[512 + tid] = bet[tid]; sPar[768 + tid] = PH ? lw[tid] : 0.f;
    }

    float acc[2][8][4];
    #pragma unroll
    for (int a = 0; a < 2; a++)
        #pragma unroll
        for (int b = 0; b < 8; b++)
            #pragma unroll
            for (int c = 0; c < 4; c++) acc[a][b][c] = 0.f;

    load_chunk(sb, 0, A, W, mBase, tid);
    cp_commit();

    for (int i = 0; i < NCH; i++) {
        if (i + 1 < NCH) {
            load_chunk(sb + ((i + 1) & 1) * STG, i + 1, A, W, mBase, tid);
            cp_commit();
            cp_wait1();
        } else {
            cp_wait0();
        }
        __syncthreads();
        const uint32_t st = sb + (i & 1) * STG;
        const uint32_t aT = st, wT = st + A_TILE;
        #pragma unroll
        for (int ks = 0; ks < 4; ks++) {
            const int kb = ks * 32;
            uint32_t bf[8][2];
            #pragma unroll
            for (int nj = 0; nj < 8; nj++) {
                uint32_t ad = (uint32_t)(nw * 64 + nj * 8 + (lane & 7)) * PITCH
                              + kb + ((lane >> 3) & 1) * 16;
                ldsm_x2(bf[nj], wT + ad);
            }
            #pragma unroll
            for (int mi = 0; mi < 2; mi++) {
                uint32_t ad = (uint32_t)(mw * 32 + mi * 16 + (lane & 7) + ((lane >> 3) & 1) * 8) * PITCH
                              + kb + ((lane >> 4) & 1) * 16;
                uint32_t af[4];
                ldsm_x4(af, aT + ad);
                #pragma unroll
                for (int nj = 0; nj < 8; nj++)
                    mma_f16(acc[mi][nj], af, bf[nj]);
            }
        }
        __syncthreads();
    }

    // ---- epilogue: bias + LN partials (4 column-groups via nw) ----
    #pragma unroll
    for (int mi = 0; mi < 2; mi++)
        #pragma unroll
        for (int rh = 0; rh < 2; rh++) {
            float s = 0.f, q = 0.f;
            #pragma unroll
            for (int nj = 0; nj < 8; nj++)
                #pragma unroll
                for (int h = 0; h < 2; h++) {
                    int col = nw * 64 + nj * 8 + 2 * (lane & 3) + h;
                    float v = acc[mi][nj][rh * 2 + h] + sPar[col];
                    acc[mi][nj][rh * 2 + h] = v;
                    s += v; q = fmaf(v, v, q);
                }
            s += __shfl_xor_sync(0xffffffffu, s, 1); s += __shfl_xor_sync(0xffffffffu, s, 2);
            q += __shfl_xor_sync(0xffffffffu, q, 1); q += __shfl_xor_sync(0xffffffffu, q, 2);
            if ((lane & 3) == 0) {
                int r = mw * 32 + mi * 16 + rh * 8 + (lane >> 2);
                sSum[nw * 128 + r] = s; sSq[nw * 128 + r] = q;
            }
        }
    __syncthreads();

    float lacc[2][2];
    #pragma unroll
    for (int mi = 0; mi < 2; mi++)
        #pragma unroll
        for (int rh = 0; rh < 2; rh++) {
            int r = mw * 32 + mi * 16 + rh * 8 + (lane >> 2);
            float tot = sSum[r] + sSum[128 + r] + sSum[256 + r] + sSum[384 + r];
            float tq  = sSq[r]  + sSq[128 + r]  + sSq[256 + r]  + sSq[384 + r];
            float mu = tot * (1.f / 256.f);
            float rstd = rsqrtf(tq * (1.f / 256.f) - mu * mu + 1e-5f);
            int rG = mBase + r;
            float la = 0.f;
            #pragma unroll
            for (int nj = 0; nj < 8; nj++) {
                int col0 = nw * 64 + nj * 8 + 2 * (lane & 3);
                float v0 = acc[mi][nj][rh * 2 + 0], v1 = acc[mi][nj][rh * 2 + 1];
                float o0 = fmaxf(0.f, fmaf((v0 - mu) * rstd, sPar[256 + col0],     sPar[512 + col0]));
                float o1 = fmaxf(0.f, fmaf((v1 - mu) * rstd, sPar[256 + col0 + 1], sPar[512 + col0 + 1]));
                if (PH == 0) {
                    __half2 hx = __floats2half2_rn(o0, o1);
                    *(uint32_t*)(g_h1h + (size_t)rG * 256 + col0) = *(uint32_t*)&hx;
                } else {
                    la = fmaf(o0, sPar[768 + col0], la);
                    la = fmaf(o1, sPar[768 + col0 + 1], la);
                }
            }
            lacc[mi][rh] = la;
        }

    if (PH == 1) {
        #pragma unroll
        for (int mi = 0; mi < 2; mi++)
            #pragma unroll
            for (int rh = 0; rh < 2; rh++) {
                float la = lacc[mi][rh];
                la += __shfl_xor_sync(0xffffffffu, la, 1);
                la += __shfl_xor_sync(0xffffffffu, la, 2);
                if ((lane & 3) == 0)
                    sLin[nw * 128 + mw * 32 + mi * 16 + rh * 8 + (lane >> 2)] = la;
            }
        __syncthreads();
        if (nw == 0 && (lane & 3) == 0) {
            #pragma unroll
            for (int mi = 0; mi < 2; mi++)
                #pragma unroll
                for (int rh = 0; rh < 2; rh++) {
                    int r = mw * 32 + mi * 16 + rh * 8 + (lane >> 2);
                    float t = sLin[r] + sLin[128 + r] + sLin[256 + r] + sLin[384 + r];
                    pred[mBase + r] = fmaxf(0.f, t + lbp[0]);
                }
        }
    }
}

// ---- rowmap + gather (unchanged, proven) ----
__global__ __launch_bounds__(512) void rowmap_k(const float* __restrict__ target, int L) {
    int b = blockIdx.x, s = threadIdx.x;
    int lane = s & 31, wp = s >> 5;
    int d = (int)rintf(target[b * 512 + s]);
    int v = d;
    #pragma unroll
    for (int o = 1; o < 32; o <<= 1) {
        int t = __shfl_up_sync(0xffffffffu, v, o);
        if (lane >= o) v += t;
    }
    __shared__ int wsum[16];
    if (lane == 31) wsum[wp] = v;
    __syncthreads();
    if (s < 16) {
        int w = wsum[s];
        #pragma unroll
        for (int o = 1; o < 16; o <<= 1) {
            int t = __shfl_up_sync(0x0000ffffu, w, o);
            if (s >= o) w += t;
        }
        wsum[s] = w;
    }
    __syncthreads();
    int end = v + (wp ? wsum[wp - 1] : 0);
    int start = end - d;
    int* rm = g_rowmap + (size_t)b * L;
    for (int l = s; l < L; l += 512) rm[l] = -1;
    __syncthreads();
    if (start < L) {
        int e = min(end, L);
        for (int l = start; l < e; ++l) rm[l] = s;
    }
}

__global__ __launch_bounds__(256) void gather_k(const float* __restrict__ x,
                                                float* __restrict__ out, int L) {
    int rowId = blockIdx.x * 4 + (threadIdx.x >> 6);
    if (rowId >= B_ * L) return;
    int t = threadIdx.x & 63;
    int b = rowId / L;
    int s = g_rowmap[rowId];
    float4 v = make_float4(0.f, 0.f, 0.f, 0.f);
    if (s >= 0)
        v = *reinterpret_cast<const float4*>(x + (size_t)((b << 9) + s) * D_ + (t << 2));
    *reinterpret_cast<float4*>(out + (size_t)rowId * D_ + (t << 2)) = v;
}

extern "C" void kernel_launch(void* const* d_in, const int* in_sizes, int n_in,
                              void* d_out, int out_size) {
    const float* x   = (const float*)d_in[0];
    const float* tgt = (const float*)d_in[1];
    const float* c1w = (const float*)d_in[2];
    const float* c1b = (const float*)d_in[3];
    const float* c2w = (const float*)d_in[4];
    const float* c2b = (const float*)d_in[5];
    const float* n1g = (const float*)d_in[6];
    const float* n1b = (const float*)d_in[7];
    const float* n2g = (const float*)d_in[8];
    const float* n2b = (const float*)d_in[9];
    const float* lw  = (const float*)d_in[10];
    const float* lb  = (const float*)d_in[11];

    float* out = (float*)d_out;
    int L = (out_size - B_ * S_) / (B_ * D_);
    float* pred = out + (size_t)B_ * L * D_;

    cudaFuncSetAttribute(conv_mma_k<0>, cudaFuncAttributeMaxDynamicSharedMemorySize, SMEM_TOTAL);
    cudaFuncSetAttribute(conv_mma_k<1>, cudaFuncAttributeMaxDynamicSharedMemorySize, SMEM_TOTAL);

    cvt_x_k<<<BS_ * D_ / 4 / 256, 256>>>(x);
    cvt_w_k<<<2 * F_ * KK_ / 256, 256>>>(c1w, c2w);

    conv_mma_k<0><<<128, 512, SMEM_TOTAL>>>(c1b, n1g, n1b, lw, lb, pred);
    conv_mma_k<1><<<128, 512, SMEM_TOTAL>>>(c2b, n2g, n2b, lw, lb, pred);

    rowmap_k<<<B_, 512>>>(tgt, L);
    gather_k<<<(B_ * L + 3) / 4, 256>>>(x, out, L);
}

// round 7
// speedup vs baseline: 4.8800x; 1.1325x over previous
#include <cuda_runtime.h>
#include <cuda_fp16.h>
#include <cstdint>

#define B_  32
#define S_  512
#define D_  256
#define F_  256
#define BS_ 16384
#define KK_ 768
#define NCH 12
#define PLANE_ROWS 16386           // 1 zero guard row each side
#define PLANE_B (PLANE_ROWS*128)   // bytes per channel-group plane
#define A_TILE 16384               // 128 rows x 128B, dense, pre-swizzled
#define W_TILE 32768               // 256 rows x 128B
#define STG (A_TILE + W_TILE)      // 49152
#define OFF_PAR (2*STG)            // 98304
#define OFF_SUM (OFF_PAR + 4096)
#define OFF_SQ  (OFF_SUM + 2048)
#define OFF_LIN (OFF_SQ  + 2048)
#define OFF_MBAR (OFF_LIN + 2048)
#define SMEM_TOTAL (OFF_MBAR + 64 + 128)   // +slack for 128B tile alignment

// staging (zero-initialized device globals; guards stay zero forever)
__device__ char g_xa [4*PLANE_B];          // x,  4 ch-group planes, swizzled
__device__ char g_h1a[4*PLANE_B];          // h1, same layout
__device__ char g_w1s[NCH*W_TILE];         // w1, chunked+swizzled
__device__ char g_w2s[NCH*W_TILE];
__device__ int  g_rowmap[B_*4608];

__device__ __forceinline__ uint32_t smem_u32(const void* p) {
    uint32_t a;
    asm("{ .reg .u64 t; cvta.to.shared.u64 t, %1; cvt.u32.u64 %0, t; }" : "=r"(a) : "l"(p));
    return a;
}
#define MBAR_INIT(a, c) asm volatile("mbarrier.init.shared.b64 [%0], %1;" :: "r"((uint32_t)(a)), "r"((uint32_t)(c)) : "memory")
#define MBAR_EXPECT(a, b) asm volatile("mbarrier.arrive.expect_tx.shared.b64 _, [%0], %1;" :: "r"((uint32_t)(a)), "r"((uint32_t)(b)) : "memory")
#define MBAR_WAIT(a, ph) do { \
    uint32_t _m = (uint32_t)(a), _p = (uint32_t)(ph), _d; \
    asm volatile("{ .reg .pred p; mbarrier.try_wait.parity.acquire.cta.shared::cta.b64 p, [%1], %2; selp.b32 %0, 1, 0, p; }" \
        : "=r"(_d) : "r"(_m), "r"(_p) : "memory"); \
    if (!_d) { asm volatile("{ .reg .pred P1;\nWL_%=:\n" \
        "mbarrier.try_wait.parity.acquire.cta.shared::cta.b64 P1, [%0], %1, 0x989680;\n" \
        "@P1 bra.uni WD_%=;\nbra.uni WL_%=;\nWD_%=:\n}" :: "r"(_m), "r"(_p) : "memory"); } \
} while (0)
__device__ __forceinline__ void bulk_cp(uint32_t dst, const void* src, uint32_t bytes, uint32_t mbar) {
    asm volatile("cp.async.bulk.shared::cta.global.mbarrier::complete_tx::bytes [%0], [%1], %2, [%3];"
        :: "r"(dst), "l"(src), "r"(bytes), "r"(mbar) : "memory");
}
__device__ __forceinline__ void ldsm_x4(uint32_t* r, uint32_t a) {
    asm volatile("ldmatrix.sync.aligned.m8n8.x4.shared.b16 {%0,%1,%2,%3}, [%4];"
        : "=r"(r[0]), "=r"(r[1]), "=r"(r[2]), "=r"(r[3]) : "r"(a));
}
__device__ __forceinline__ void mma_f16(float* d, const uint32_t* a, const uint32_t* b) {
    asm volatile("mma.sync.aligned.m16n8k16.row.col.f32.f16.f16.f32 "
        "{%0,%1,%2,%3}, {%4,%5,%6,%7}, {%8,%9}, {%0,%1,%2,%3};"
        : "+f"(d[0]), "+f"(d[1]), "+f"(d[2]), "+f"(d[3])
        : "r"(a[0]), "r"(a[1]), "r"(a[2]), "r"(a[3]), "r"(b[0]), "r"(b[1]));
}

// ---- prep: x -> swizzled channel-group planes (guard row offset +1) ----
__global__ __launch_bounds__(256) void cvt_x_k(const float* __restrict__ x) {
    int i = blockIdx.x * 256 + threadIdx.x;       // BS_*D_/2 uint32 items
    int R = i >> 7, cp = i & 127;                  // cp: pair of channels
    float2 v = reinterpret_cast<const float2*>(x)[(size_t)R * 128 + cp];
    __half2 h = __floats2half2_rn(v.x, v.y);
    int cg = cp >> 5;
    int prow = R + 1;
    uint32_t byte = (uint32_t)(4 * (cp & 31)) ^ (uint32_t)((prow & 7) << 4);
    *reinterpret_cast<uint32_t*>(g_xa + (size_t)cg * PLANE_B + (size_t)prow * 128 + byte)
        = *reinterpret_cast<uint32_t*>(&h);
}
// ---- prep: weights -> chunked+swizzled [12][256][128B] ----
__global__ __launch_bounds__(256) void cvt_w_k(const float* __restrict__ w1,
                                               const float* __restrict__ w2) {
    int gid = blockIdx.x * 256 + threadIdx.x;      // 2 * F*KK items
    int ph = gid >= F_ * KK_;
    int idx = ph ? gid - F_ * KK_ : gid;
    int f = idx / 768, rem = idx - f * 768;
    int tap = rem >> 8, c = rem & 255;
    int kk = tap * 256 + c;                        // dest kk index
    int chunk = kk >> 6, kc = kk & 63;
    const float* w = ph ? w2 : w1;
    __half hv = __float2half(w[f * 768 + c * 3 + tap]);
    uint32_t byte = (uint32_t)(2 * kc) ^ (uint32_t)((f & 7) << 4);
    *reinterpret_cast<__half*>((ph ? g_w2s : g_w1s)
        + (size_t)chunk * W_TILE + (size_t)f * 128 + byte) = hv;
}

// ---- fused conv GEMM (fp16 HMMA, 16 warps, TMA bulk loads) ----
template<int PH>
__global__ __launch_bounds__(512) void conv_mma_k(
    const float* __restrict__ bias, const float* __restrict__ gam,
    const float* __restrict__ bet, const float* __restrict__ lw,
    const float* __restrict__ lbp, float* __restrict__ pred)
{
    extern __shared__ char smem[];
    const uint32_t sb0 = smem_u32(smem);
    const uint32_t tiles = (sb0 + 127) & ~127u;
    char* smc = smem + (tiles - sb0);
    float* sPar = (float*)(smc + OFF_PAR);
    float* sSum = (float*)(smc + OFF_SUM);
    float* sSq  = (float*)(smc + OFF_SQ);
    float* sLin = (float*)(smc + OFF_LIN);
    const uint32_t mb = tiles + OFF_MBAR;          // two 8B mbarriers
    const int tid = threadIdx.x, lane = tid & 31, warp = tid >> 5;
    const int mw = warp >> 2, nw = warp & 3;       // 4x4 warps, warp tile 32x64
    const int mBase = blockIdx.x * 128;

    const char* Apl = PH ? g_h1a : g_xa;
    const char* Wst = PH ? g_w2s : g_w1s;

    if (tid < 256) {
        sPar[tid] = bias[tid]; sPar[256 + tid] = gam[tid];
        sPar[512 + tid] = bet[tid]; sPar[768 + tid] = PH ? lw[tid] : 0.f;
    }
    if (tid == 0) { MBAR_INIT(mb, 1); MBAR_INIT(mb + 8, 1); }
    __syncthreads();

    // issue chunk 0 into stage 0
    if (tid == 0) {
        MBAR_EXPECT(mb, STG);
        bulk_cp(tiles, Apl + (size_t)0 * PLANE_B + (size_t)(mBase + 0) * 128, A_TILE, mb);
        bulk_cp(tiles + A_TILE, Wst, W_TILE, mb);
    }

    float acc[2][8][4];
    #pragma unroll
    for (int a = 0; a < 2; a++)
        #pragma unroll
        for (int b = 0; b < 8; b++)
            #pragma unroll
            for (int c = 0; c < 4; c++) acc[a][b][c] = 0.f;

    int pha[2] = {0, 0};
    const bool fix0 = ((mBase & 511) == 0);        // tap0 pulls row from prev batch
    const bool fix2 = (((mBase + 128) & 511) == 0);// tap2 pulls row from next batch

    for (int i = 0; i < NCH; i++) {
        const int st = i & 1;
        const int tap = i >> 2;
        if (i + 1 < NCH && tid == 0) {             // stage st^1 free (synced last iter)
            const int nc = i + 1, ntap = nc >> 2, ncg = nc & 3;
            const uint32_t nb = tiles + (st ^ 1) * STG;
            const uint32_t nmb = mb + 8 * (st ^ 1);
            MBAR_EXPECT(nmb, STG);
            bulk_cp(nb, Apl + (size_t)ncg * PLANE_B + (size_t)(mBase + ntap) * 128, A_TILE, nmb);
            bulk_cp(nb + A_TILE, Wst + (size_t)nc * W_TILE, W_TILE, nmb);
        }
        MBAR_WAIT(mb + 8 * st, pha[st]); pha[st] ^= 1;
        const uint32_t aT = tiles + st * STG, wT = aT + A_TILE;
        // 'same'-padding fixup at batch boundaries: zero one smem A row
        if (tap == 0 && fix0 && tid < 8)
            *reinterpret_cast<uint4*>(smc + st * STG + tid * 16) = make_uint4(0, 0, 0, 0);
        if (tap == 2 && fix2 && tid < 8)
            *reinterpret_cast<uint4*>(smc + st * STG + 127 * 128 + tid * 16) = make_uint4(0, 0, 0, 0);
        __syncthreads();

        #pragma unroll
        for (int ks = 0; ks < 4; ks++) {
            uint32_t bf[8][2];
            #pragma unroll
            for (int njp = 0; njp < 4; njp++) {    // 2 nj per ldsm_x4
                int f = nw * 64 + (2 * njp + ((lane >> 4) & 1)) * 8 + (lane & 7);
                int kseg = ks * 2 + ((lane >> 3) & 1);
                uint32_t ad = wT + (uint32_t)f * 128 + (uint32_t)((kseg ^ (f & 7)) << 4);
                uint32_t r[4];
                ldsm_x4(r, ad);
                bf[2 * njp][0] = r[0]; bf[2 * njp][1] = r[1];
                bf[2 * njp + 1][0] = r[2]; bf[2 * njp + 1][1] = r[3];
            }
            #pragma unroll
            for (int mi = 0; mi < 2; mi++) {
                int j = mw * 32 + mi * 16 + (lane & 7) + ((lane >> 3) & 1) * 8;
                int kseg = ks * 2 + ((lane >> 4) & 1);
                uint32_t ad = aT + (uint32_t)j * 128 + (uint32_t)((kseg ^ ((j + tap) & 7)) << 4);
                uint32_t af[4];
                ldsm_x4(af, ad);
                #pragma unroll
                for (int nj = 0; nj < 8; nj++)
                    mma_f16(acc[mi][nj], af, bf[nj]);
            }
        }
        __syncthreads();
    }

    // ---- epilogue: bias + LN partials ----
    #pragma unroll
    for (int mi = 0; mi < 2; mi++)
        #pragma unroll
        for (int rh = 0; rh < 2; rh++) {
            float s = 0.f, q = 0.f;
            #pragma unroll
            for (int nj = 0; nj < 8; nj++)
                #pragma unroll
                for (int h = 0; h < 2; h++) {
                    int col = nw * 64 + nj * 8 + 2 * (lane & 3) + h;
                    float v = acc[mi][nj][rh * 2 + h] + sPar[col];
                    acc[mi][nj][rh * 2 + h] = v;
                    s += v; q = fmaf(v, v, q);
                }
            s += __shfl_xor_sync(0xffffffffu, s, 1); s += __shfl_xor_sync(0xffffffffu, s, 2);
            q += __shfl_xor_sync(0xffffffffu, q, 1); q += __shfl_xor_sync(0xffffffffu, q, 2);
            if ((lane & 3) == 0) {
                int r = mw * 32 + mi * 16 + rh * 8 + (lane >> 2);
                sSum[nw * 128 + r] = s; sSq[nw * 128 + r] = q;
            }
        }
    __syncthreads();

    float lacc[2][2];
    #pragma unroll
    for (int mi = 0; mi < 2; mi++)
        #pragma unroll
        for (int rh = 0; rh < 2; rh++) {
            int r = mw * 32 + mi * 16 + rh * 8 + (lane >> 2);
            float tot = sSum[r] + sSum[128 + r] + sSum[256 + r] + sSum[384 + r];
            float tq  = sSq[r]  + sSq[128 + r]  + sSq[256 + r]  + sSq[384 + r];
            float mu = tot * (1.f / 256.f);
            float rstd = rsqrtf(tq * (1.f / 256.f) - mu * mu + 1e-5f);
            int rG = mBase + r;
            float la = 0.f;
            #pragma unroll
            for (int nj = 0; nj < 8; nj++) {
                int col0 = nw * 64 + nj * 8 + 2 * (lane & 3);
                float v0 = acc[mi][nj][rh * 2 + 0], v1 = acc[mi][nj][rh * 2 + 1];
                float o0 = fmaxf(0.f, fmaf((v0 - mu) * rstd, sPar[256 + col0],     sPar[512 + col0]));
                float o1 = fmaxf(0.f, fmaf((v1 - mu) * rstd, sPar[256 + col0 + 1], sPar[512 + col0 + 1]));
                if (PH == 0) {
                    __half2 hx = __floats2half2_rn(o0, o1);
                    int prow = rG + 1;
                    uint32_t byte = (uint32_t)(2 * (col0 & 63)) ^ (uint32_t)((prow & 7) << 4);
                    *reinterpret_cast<uint32_t*>(g_h1a + (size_t)nw * PLANE_B
                        + (size_t)prow * 128 + byte) = *reinterpret_cast<uint32_t*>(&hx);
                } else {
                    la = fmaf(o0, sPar[768 + col0], la);
                    la = fmaf(o1, sPar[768 + col0 + 1], la);
                }
            }
            lacc[mi][rh] = la;
        }

    if (PH == 1) {
        #pragma unroll
        for (int mi = 0; mi < 2; mi++)
            #pragma unroll
            for (int rh = 0; rh < 2; rh++) {
                float la = lacc[mi][rh];
                la += __shfl_xor_sync(0xffffffffu, la, 1);
                la += __shfl_xor_sync(0xffffffffu, la, 2);
                if ((lane & 3) == 0)
                    sLin[nw * 128 + mw * 32 + mi * 16 + rh * 8 + (lane >> 2)] = la;
            }
        __syncthreads();
        if (nw == 0 && (lane & 3) == 0) {
            #pragma unroll
            for (int mi = 0; mi < 2; mi++)
                #pragma unroll
                for (int rh = 0; rh < 2; rh++) {
                    int r = mw * 32 + mi * 16 + rh * 8 + (lane >> 2);
                    float t = sLin[r] + sLin[128 + r] + sLin[256 + r] + sLin[384 + r];
                    pred[mBase + r] = fmaxf(0.f, t + lbp[0]);
                }
        }
    }
}

// ---- rowmap + gather (unchanged, proven) ----
__global__ __launch_bounds__(512) void rowmap_k(const float* __restrict__ target, int L) {
    int b = blockIdx.x, s = threadIdx.x;
    int lane = s & 31, wp = s >> 5;
    int d = (int)rintf(target[b * 512 + s]);
    int v = d;
    #pragma unroll
    for (int o = 1; o < 32; o <<= 1) {
        int t = __shfl_up_sync(0xffffffffu, v, o);
        if (lane >= o) v += t;
    }
    __shared__ int wsum[16];
    if (lane == 31) wsum[wp] = v;
    __syncthreads();
    if (s < 16) {
        int w = wsum[s];
        #pragma unroll
        for (int o = 1; o < 16; o <<= 1) {
            int t = __shfl_up_sync(0x0000ffffu, w, o);
            if (s >= o) w += t;
        }
        wsum[s] = w;
    }
    __syncthreads();
    int end = v + (wp ? wsum[wp - 1] : 0);
    int start = end - d;
    int* rm = g_rowmap + (size_t)b * L;
    for (int l = s; l < L; l += 512) rm[l] = -1;
    __syncthreads();
    if (start < L) {
        int e = min(end, L);
        for (int l = start; l < e; ++l) rm[l] = s;
    }
}

__global__ __launch_bounds__(256) void gather_k(const float* __restrict__ x,
                                                float* __restrict__ out, int L) {
    int rowId = blockIdx.x * 4 + (threadIdx.x >> 6);
    if (rowId >= B_ * L) return;
    int t = threadIdx.x & 63;
    int b = rowId / L;
    int s = g_rowmap[rowId];
    float4 v = make_float4(0.f, 0.f, 0.f, 0.f);
    if (s >= 0)
        v = *reinterpret_cast<const float4*>(x + (size_t)((b << 9) + s) * D_ + (t << 2));
    *reinterpret_cast<float4*>(out + (size_t)rowId * D_ + (t << 2)) = v;
}

extern "C" void kernel_launch(void* const* d_in, const int* in_sizes, int n_in,
                              void* d_out, int out_size) {
    const float* x   = (const float*)d_in[0];
    const float* tgt = (const float*)d_in[1];
    const float* c1w = (const float*)d_in[2];
    const float* c1b = (const float*)d_in[3];
    const float* c2w = (const float*)d_in[4];
    const float* c2b = (const float*)d_in[5];
    const float* n1g = (const float*)d_in[6];
    const float* n1b = (const float*)d_in[7];
    const float* n2g = (const float*)d_in[8];
    const float* n2b = (const float*)d_in[9];
    const float* lw  = (const float*)d_in[10];
    const float* lb  = (const float*)d_in[11];

    float* out = (float*)d_out;
    int L = (out_size - B_ * S_) / (B_ * D_);
    float* pred = out + (size_t)B_ * L * D_;

    cudaFuncSetAttribute(conv_mma_k<0>, cudaFuncAttributeMaxDynamicSharedMemorySize, SMEM_TOTAL);
    cudaFuncSetAttribute(conv_mma_k<1>, cudaFuncAttributeMaxDynamicSharedMemorySize, SMEM_TOTAL);

    cvt_x_k<<<BS_ * D_ / 2 / 256, 256>>>(x);
    cvt_w_k<<<2 * F_ * KK_ / 256, 256>>>(c1w, c2w);

    conv_mma_k<0><<<128, 512, SMEM_TOTAL>>>(c1b, n1g, n1b, lw, lb, pred);
    conv_mma_k<1><<<128, 512, SMEM_TOTAL>>>(c2b, n2g, n2b, lw, lb, pred);

    rowmap_k<<<B_, 512>>>(tgt, L);
    gather_k<<<(B_ * L + 3) / 4, 256>>>(x, out, L);
}

// round 8
// speedup vs baseline: 5.2861x; 1.0832x over previous
#include <cuda_runtime.h>
#include <cuda_fp16.h>
#include <cstdint>

#define B_  32
#define S_  512
#define D_  256
#define F_  256
#define BS_ 16384
#define KK_ 768
#define NCH 12
#define NSTG 4
#define PLANE_ROWS 16386           // 1 zero guard row each side
#define PLANE_B (PLANE_ROWS*128)
#define A_TILE 16384               // 128 rows x 128B, pre-swizzled
#define W_TILE 32768               // 256 rows x 128B
#define STG 49152                  // A_TILE + W_TILE
#define OFF_PAR (NSTG*STG)         // 196608
#define OFF_SUM (OFF_PAR + 4096)
#define OFF_SQ  (OFF_SUM + 2048)
#define OFF_LIN (OFF_SQ  + 2048)
#define OFF_MBAR (OFF_LIN + 2048)
#define SMEM_TOTAL (OFF_MBAR + 64 + 128)

__device__ char g_xa [4*PLANE_B];
__device__ char g_h1a[4*PLANE_B];
__device__ char g_w1s[NCH*W_TILE];
__device__ char g_w2s[NCH*W_TILE];
__device__ int  g_rowmap[B_*4608];

__device__ __forceinline__ uint32_t smem_u32(const void* p) {
    uint32_t a;
    asm("{ .reg .u64 t; cvta.to.shared.u64 t, %1; cvt.u32.u64 %0, t; }" : "=r"(a) : "l"(p));
    return a;
}
#define MBAR_INIT(a, c) asm volatile("mbarrier.init.shared.b64 [%0], %1;" :: "r"((uint32_t)(a)), "r"((uint32_t)(c)) : "memory")
#define MBAR_EXPECT(a, b) asm volatile("mbarrier.arrive.expect_tx.shared.b64 _, [%0], %1;" :: "r"((uint32_t)(a)), "r"((uint32_t)(b)) : "memory")
#define MBAR_WAIT(a, ph) do { \
    uint32_t _m = (uint32_t)(a), _p = (uint32_t)(ph), _d; \
    asm volatile("{ .reg .pred p; mbarrier.try_wait.parity.acquire.cta.shared::cta.b64 p, [%1], %2; selp.b32 %0, 1, 0, p; }" \
        : "=r"(_d) : "r"(_m), "r"(_p) : "memory"); \
    if (!_d) { asm volatile("{ .reg .pred P1;\nWL_%=:\n" \
        "mbarrier.try_wait.parity.acquire.cta.shared::cta.b64 P1, [%0], %1, 0x989680;\n" \
        "@P1 bra.uni WD_%=;\nbra.uni WL_%=;\nWD_%=:\n}" :: "r"(_m), "r"(_p) : "memory"); } \
} while (0)
__device__ __forceinline__ void bulk_cp(uint32_t dst, const void* src, uint32_t bytes, uint32_t mbar) {
    asm volatile("cp.async.bulk.shared::cta.global.mbarrier::complete_tx::bytes [%0], [%1], %2, [%3];"
        :: "r"(dst), "l"(src), "r"(bytes), "r"(mbar) : "memory");
}
__device__ __forceinline__ void ldsm_x4(uint32_t* r, uint32_t a) {
    asm volatile("ldmatrix.sync.aligned.m8n8.x4.shared.b16 {%0,%1,%2,%3}, [%4];"
        : "=r"(r[0]), "=r"(r[1]), "=r"(r[2]), "=r"(r[3]) : "r"(a));
}
__device__ __forceinline__ void mma_f16(float* d, const uint32_t* a, const uint32_t* b) {
    asm volatile("mma.sync.aligned.m16n8k16.row.col.f32.f16.f16.f32 "
        "{%0,%1,%2,%3}, {%4,%5,%6,%7}, {%8,%9}, {%0,%1,%2,%3};"
        : "+f"(d[0]), "+f"(d[1]), "+f"(d[2]), "+f"(d[3])
        : "r"(a[0]), "r"(a[1]), "r"(a[2]), "r"(a[3]), "r"(b[0]), "r"(b[1]));
}

// ---- prep: x -> swizzled channel-group planes ----
__global__ __launch_bounds__(256) void cvt_x_k(const float* __restrict__ x) {
    int i = blockIdx.x * 256 + threadIdx.x;
    int R = i >> 7, cp = i & 127;
    float2 v = reinterpret_cast<const float2*>(x)[(size_t)R * 128 + cp];
    __half2 h = __floats2half2_rn(v.x, v.y);
    int cg = cp >> 5;
    int prow = R + 1;
    uint32_t byte = (uint32_t)(4 * (cp & 31)) ^ (uint32_t)((prow & 7) << 4);
    *reinterpret_cast<uint32_t*>(g_xa + (size_t)cg * PLANE_B + (size_t)prow * 128 + byte)
        = *reinterpret_cast<uint32_t*>(&h);
}
// ---- prep: weights -> chunked+swizzled ----
__global__ __launch_bounds__(256) void cvt_w_k(const float* __restrict__ w1,
                                               const float* __restrict__ w2) {
    int gid = blockIdx.x * 256 + threadIdx.x;
    int ph = gid >= F_ * KK_;
    int idx = ph ? gid - F_ * KK_ : gid;
    int f = idx / 768, rem = idx - f * 768;
    int tap = rem >> 8, c = rem & 255;
    int kk = tap * 256 + c;
    int chunk = kk >> 6, kc = kk & 63;
    const float* w = ph ? w2 : w1;
    __half hv = __float2half(w[f * 768 + c * 3 + tap]);
    uint32_t byte = (uint32_t)(2 * kc) ^ (uint32_t)((f & 7) << 4);
    *reinterpret_cast<__half*>((ph ? g_w2s : g_w1s)
        + (size_t)chunk * W_TILE + (size_t)f * 128 + byte) = hv;
}

// ---- fused conv GEMM (fp16 HMMA, 16 warps, 4-stage bulk pipeline) ----
template<int PH>
__global__ __launch_bounds__(512) void conv_mma_k(
    const float* __restrict__ bias, const float* __restrict__ gam,
    const float* __restrict__ bet, const float* __restrict__ lw,
    const float* __restrict__ lbp, float* __restrict__ pred)
{
    extern __shared__ char smem[];
    const uint32_t sb0 = smem_u32(smem);
    const uint32_t tiles = (sb0 + 127) & ~127u;
    char* smc = smem + (tiles - sb0);
    float* sPar = (float*)(smc + OFF_PAR);
    float* sSum = (float*)(smc + OFF_SUM);
    float* sSq  = (float*)(smc + OFF_SQ);
    float* sLin = (float*)(smc + OFF_LIN);
    const uint32_t mb = tiles + OFF_MBAR;
    const int tid = threadIdx.x, lane = tid & 31, warp = tid >> 5;
    const int mw = warp >> 2, nw = warp & 3;
    const int mBase = blockIdx.x * 128;

    const char* Apl = PH ? g_h1a : g_xa;
    const char* Wst = PH ? g_w2s : g_w1s;

    if (tid < 256) {
        sPar[tid] = bias[tid]; sPar[256 + tid] = gam[tid];
        sPar[512 + tid] = bet[tid]; sPar[768 + tid] = PH ? lw[tid] : 0.f;
    }
    if (tid == 0) {
        #pragma unroll
        for (int s = 0; s < NSTG; s++) MBAR_INIT(mb + 8 * s, 1);
    }
    __syncthreads();

    if (tid == 0) {
        #pragma unroll
        for (int j = 0; j < 3; j++) {            // prologue: chunks 0..2
            const int tap = j >> 2, cg = j & 3;
            MBAR_EXPECT(mb + 8 * j, STG);
            bulk_cp(tiles + j * STG, Apl + (size_t)cg * PLANE_B + (size_t)(mBase + tap) * 128,
                    A_TILE, mb + 8 * j);
            bulk_cp(tiles + j * STG + A_TILE, Wst + (size_t)j * W_TILE, W_TILE, mb + 8 * j);
        }
    }

    float acc[2][8][4];
    #pragma unroll
    for (int a = 0; a < 2; a++)
        #pragma unroll
        for (int b = 0; b < 8; b++)
            #pragma unroll
            for (int c = 0; c < 4; c++) acc[a][b][c] = 0.f;

    int pha[NSTG] = {0, 0, 0, 0};
    const bool fix0 = ((mBase & 511) == 0);
    const bool fix2 = (((mBase + 128) & 511) == 0);

    for (int i = 0; i < NCH; i++) {
        const int st = i & 3;
        const int tap = i >> 2;
        __syncthreads();                          // stage (i-1)&3 fully drained
        if (tid == 0 && i + 3 < NCH) {
            const int nc = i + 3, ntap = nc >> 2, ncg = nc & 3, nst = nc & 3;
            MBAR_EXPECT(mb + 8 * nst, STG);
            bulk_cp(tiles + nst * STG, Apl + (size_t)ncg * PLANE_B + (size_t)(mBase + ntap) * 128,
                    A_TILE, mb + 8 * nst);
            bulk_cp(tiles + nst * STG + A_TILE, Wst + (size_t)nc * W_TILE, W_TILE, mb + 8 * nst);
        }
        MBAR_WAIT(mb + 8 * st, pha[st]); pha[st] ^= 1;
        const uint32_t aT = tiles + st * STG, wT = aT + A_TILE;
        // 'same'-padding fixup: reading warps zero the boundary row themselves
        // (redundant same-value stores across warps are benign)
        if (tap == 0 && fix0 && mw == 0 && lane < 8)
            *reinterpret_cast<uint4*>(smc + st * STG + lane * 16) = make_uint4(0, 0, 0, 0);
        if (tap == 2 && fix2 && mw == 3 && lane < 8)
            *reinterpret_cast<uint4*>(smc + st * STG + 127 * 128 + lane * 16) = make_uint4(0, 0, 0, 0);
        __syncwarp();

        #pragma unroll
        for (int ks = 0; ks < 4; ks++) {
            uint32_t bf[8][2];
            #pragma unroll
            for (int njp = 0; njp < 4; njp++) {
                int f = nw * 64 + (2 * njp + ((lane >> 4) & 1)) * 8 + (lane & 7);
                int kseg = ks * 2 + ((lane >> 3) & 1);
                uint32_t ad = wT + (uint32_t)f * 128 + (uint32_t)((kseg ^ (f & 7)) << 4);
                uint32_t r[4];
                ldsm_x4(r, ad);
                bf[2 * njp][0] = r[0]; bf[2 * njp][1] = r[1];
                bf[2 * njp + 1][0] = r[2]; bf[2 * njp + 1][1] = r[3];
            }
            #pragma unroll
            for (int mi = 0; mi < 2; mi++) {
                int j = mw * 32 + mi * 16 + (lane & 7) + ((lane >> 3) & 1) * 8;
                int kseg = ks * 2 + ((lane >> 4) & 1);
                uint32_t ad = aT + (uint32_t)j * 128 + (uint32_t)((kseg ^ ((j + tap) & 7)) << 4);
                uint32_t af[4];
                ldsm_x4(af, ad);
                #pragma unroll
                for (int nj = 0; nj < 8; nj++)
                    mma_f16(acc[mi][nj], af, bf[nj]);
            }
        }
    }
    __syncthreads();

    // ---- epilogue: bias + LN partials ----
    #pragma unroll
    for (int mi = 0; mi < 2; mi++)
        #pragma unroll
        for (int rh = 0; rh < 2; rh++) {
            float s = 0.f, q = 0.f;
            #pragma unroll
            for (int nj = 0; nj < 8; nj++)
                #pragma unroll
                for (int h = 0; h < 2; h++) {
                    int col = nw * 64 + nj * 8 + 2 * (lane & 3) + h;
                    float v = acc[mi][nj][rh * 2 + h] + sPar[col];
                    acc[mi][nj][rh * 2 + h] = v;
                    s += v; q = fmaf(v, v, q);
                }
            s += __shfl_xor_sync(0xffffffffu, s, 1); s += __shfl_xor_sync(0xffffffffu, s, 2);
            q += __shfl_xor_sync(0xffffffffu, q, 1); q += __shfl_xor_sync(0xffffffffu, q, 2);
            if ((lane & 3) == 0) {
                int r = mw * 32 + mi * 16 + rh * 8 + (lane >> 2);
                sSum[nw * 128 + r] = s; sSq[nw * 128 + r] = q;
            }
        }
    __syncthreads();

    float lacc[2][2];
    #pragma unroll
    for (int mi = 0; mi < 2; mi++)
        #pragma unroll
        for (int rh = 0; rh < 2; rh++) {
            int r = mw * 32 + mi * 16 + rh * 8 + (lane >> 2);
            float tot = sSum[r] + sSum[128 + r] + sSum[256 + r] + sSum[384 + r];
            float tq  = sSq[r]  + sSq[128 + r]  + sSq[256 + r]  + sSq[384 + r];
            float mu = tot * (1.f / 256.f);
            float rstd = rsqrtf(tq * (1.f / 256.f) - mu * mu + 1e-5f);
            int rG = mBase + r;
            float la = 0.f;
            #pragma unroll
            for (int nj = 0; nj < 8; nj++) {
                int col0 = nw * 64 + nj * 8 + 2 * (lane & 3);
                float v0 = acc[mi][nj][rh * 2 + 0], v1 = acc[mi][nj][rh * 2 + 1];
                float o0 = fmaxf(0.f, fmaf((v0 - mu) * rstd, sPar[256 + col0],     sPar[512 + col0]));
                float o1 = fmaxf(0.f, fmaf((v1 - mu) * rstd, sPar[256 + col0 + 1], sPar[512 + col0 + 1]));
                if (PH == 0) {
                    __half2 hx = __floats2half2_rn(o0, o1);
                    int prow = rG + 1;
                    uint32_t byte = (uint32_t)(2 * (col0 & 63)) ^ (uint32_t)((prow & 7) << 4);
                    *reinterpret_cast<uint32_t*>(g_h1a + (size_t)nw * PLANE_B
                        + (size_t)prow * 128 + byte) = *reinterpret_cast<uint32_t*>(&hx);
                } else {
                    la = fmaf(o0, sPar[768 + col0], la);
                    la = fmaf(o1, sPar[768 + col0 + 1], la);
                }
            }
            lacc[mi][rh] = la;
        }

    if (PH == 1) {
        #pragma unroll
        for (int mi = 0; mi < 2; mi++)
            #pragma unroll
            for (int rh = 0; rh < 2; rh++) {
                float la = lacc[mi][rh];
                la += __shfl_xor_sync(0xffffffffu, la, 1);
                la += __shfl_xor_sync(0xffffffffu, la, 2);
                if ((lane & 3) == 0)
                    sLin[nw * 128 + mw * 32 + mi * 16 + rh * 8 + (lane >> 2)] = la;
            }
        __syncthreads();
        if (nw == 0 && (lane & 3) == 0) {
            #pragma unroll
            for (int mi = 0; mi < 2; mi++)
                #pragma unroll
                for (int rh = 0; rh < 2; rh++) {
                    int r = mw * 32 + mi * 16 + rh * 8 + (lane >> 2);
                    float t = sLin[r] + sLin[128 + r] + sLin[256 + r] + sLin[384 + r];
                    pred[mBase + r] = fmaxf(0.f, t + lbp[0]);
                }
        }
    }
}

// ---- rowmap + gather (unchanged, proven) ----
__global__ __launch_bounds__(512) void rowmap_k(const float* __restrict__ target, int L) {
    int b = blockIdx.x, s = threadIdx.x;
    int lane = s & 31, wp = s >> 5;
    int d = (int)rintf(target[b * 512 + s]);
    int v = d;
    #pragma unroll
    for (int o = 1; o < 32; o <<= 1) {
        int t = __shfl_up_sync(0xffffffffu, v, o);
        if (lane >= o) v += t;
    }
    __shared__ int wsum[16];
    if (lane == 31) wsum[wp] = v;
    __syncthreads();
    if (s < 16) {
        int w = wsum[s];
        #pragma unroll
        for (int o = 1; o < 16; o <<= 1) {
            int t = __shfl_up_sync(0x0000ffffu, w, o);
            if (s >= o) w += t;
        }
        wsum[s] = w;
    }
    __syncthreads();
    int end = v + (wp ? wsum[wp - 1] : 0);
    int start = end - d;
    int* rm = g_rowmap + (size_t)b * L;
    for (int l = s; l < L; l += 512) rm[l] = -1;
    __syncthreads();
    if (start < L) {
        int e = min(end, L);
        for (int l = start; l < e; ++l) rm[l] = s;
    }
}

__global__ __launch_bounds__(256) void gather_k(const float* __restrict__ x,
                                                float* __restrict__ out, int L) {
    int rowId = blockIdx.x * 4 + (threadIdx.x >> 6);
    if (rowId >= B_ * L) return;
    int t = threadIdx.x & 63;
    int b = rowId / L;
    int s = g_rowmap[rowId];
    float4 v = make_float4(0.f, 0.f, 0.f, 0.f);
    if (s >= 0)
        v = *reinterpret_cast<const float4*>(x + (size_t)((b << 9) + s) * D_ + (t << 2));
    *reinterpret_cast<float4*>(out + (size_t)rowId * D_ + (t << 2)) = v;
}

extern "C" void kernel_launch(void* const* d_in, const int* in_sizes, int n_in,
                              void* d_out, int out_size) {
    const float* x   = (const float*)d_in[0];
    const float* tgt = (const float*)d_in[1];
    const float* c1w = (const float*)d_in[2];
    const float* c1b = (const float*)d_in[3];
    const float* c2w = (const float*)d_in[4];
    const float* c2b = (const float*)d_in[5];
    const float* n1g = (const float*)d_in[6];
    const float* n1b = (const float*)d_in[7];
    const float* n2g = (const float*)d_in[8];
    const float* n2b = (const float*)d_in[9];
    const float* lw  = (const float*)d_in[10];
    const float* lb  = (const float*)d_in[11];

    float* out = (float*)d_out;
    int L = (out_size - B_ * S_) / (B_ * D_);
    float* pred = out + (size_t)B_ * L * D_;

    static cudaStream_t s2 = nullptr;
    static cudaEvent_t evF = nullptr, evJ = nullptr;
    if (s2 == nullptr) {
        cudaStreamCreateWithFlags(&s2, cudaStreamNonBlocking);
        cudaEventCreateWithFlags(&evF, cudaEventDisableTiming);
        cudaEventCreateWithFlags(&evJ, cudaEventDisableTiming);
        cudaFuncSetAttribute(conv_mma_k<0>, cudaFuncAttributeMaxDynamicSharedMemorySize, SMEM_TOTAL);
        cudaFuncSetAttribute(conv_mma_k<1>, cudaFuncAttributeMaxDynamicSharedMemorySize, SMEM_TOTAL);
    }

    // fork: length-regulator branch runs concurrently with the conv branch
    cudaEventRecord(evF, 0);
    cudaStreamWaitEvent(s2, evF, 0);
    rowmap_k<<<B_, 512, 0, s2>>>(tgt, L);
    gather_k<<<(B_ * L + 3) / 4, 256, 0, s2>>>(x, out, L);
    cudaEventRecord(evJ, s2);

    // main: duration-predictor branch
    cvt_w_k<<<2 * F_ * KK_ / 256, 256>>>(c1w, c2w);
    cvt_x_k<<<BS_ * D_ / 2 / 256, 256>>>(x);
    conv_mma_k<0><<<128, 512, SMEM_TOTAL>>>(c1b, n1g, n1b, lw, lb, pred);
    conv_mma_k<1><<<128, 512, SMEM_TOTAL>>>(c2b, n2g, n2b, lw, lb, pred);

    // join
    cudaStreamWaitEvent(0, evJ, 0);
}

// round 9
// speedup vs baseline: 5.5940x; 1.0583x over previous
#include <cuda_runtime.h>
#include <cuda_fp16.h>
#include <cstdint>

#define B_  32
#define S_  512
#define D_  256
#define F_  256
#define BS_ 16384
#define KK_ 768
#define NCH 12
#define NSTG 2
#define PLANE_ROWS 16386           // 1 zero guard row each side
#define PLANE_B (PLANE_ROWS*128)
#define A_TILE 8192                // 64 rows x 128B, pre-swizzled
#define W_TILE 32768               // 256 rows x 128B
#define STG (A_TILE + W_TILE)      // 40960
#define OFF_PAR (NSTG*STG)         // 81920
#define OFF_SUM (OFF_PAR + 4096)
#define OFF_SQ  (OFF_SUM + 1024)
#define OFF_LIN (OFF_SQ  + 1024)
#define OFF_MBAR (OFF_LIN + 1024)
#define SMEM_TOTAL (OFF_MBAR + 64 + 128)   // ~89.3KB -> 2 CTAs/SM

__device__ char g_xa [4*PLANE_B];
__device__ char g_h1a[4*PLANE_B];
__device__ char g_w1s[NCH*W_TILE];
__device__ char g_w2s[NCH*W_TILE];
__device__ int  g_rowmap[B_*4608];

__device__ __forceinline__ uint32_t smem_u32(const void* p) {
    uint32_t a;
    asm("{ .reg .u64 t; cvta.to.shared.u64 t, %1; cvt.u32.u64 %0, t; }" : "=r"(a) : "l"(p));
    return a;
}
#define MBAR_INIT(a, c) asm volatile("mbarrier.init.shared.b64 [%0], %1;" :: "r"((uint32_t)(a)), "r"((uint32_t)(c)) : "memory")
#define MBAR_EXPECT(a, b) asm volatile("mbarrier.arrive.expect_tx.shared.b64 _, [%0], %1;" :: "r"((uint32_t)(a)), "r"((uint32_t)(b)) : "memory")
#define MBAR_WAIT(a, ph) do { \
    uint32_t _m = (uint32_t)(a), _p = (uint32_t)(ph), _d; \
    asm volatile("{ .reg .pred p; mbarrier.try_wait.parity.acquire.cta.shared::cta.b64 p, [%1], %2; selp.b32 %0, 1, 0, p; }" \
        : "=r"(_d) : "r"(_m), "r"(_p) : "memory"); \
    if (!_d) { asm volatile("{ .reg .pred P1;\nWL_%=:\n" \
        "mbarrier.try_wait.parity.acquire.cta.shared::cta.b64 P1, [%0], %1, 0x989680;\n" \
        "@P1 bra.uni WD_%=;\nbra.uni WL_%=;\nWD_%=:\n}" :: "r"(_m), "r"(_p) : "memory"); } \
} while (0)
__device__ __forceinline__ void bulk_cp(uint32_t dst, const void* src, uint32_t bytes, uint32_t mbar) {
    asm volatile("cp.async.bulk.shared::cta.global.mbarrier::complete_tx::bytes [%0], [%1], %2, [%3];"
        :: "r"(dst), "l"(src), "r"(bytes), "r"(mbar) : "memory");
}
__device__ __forceinline__ void ldsm_x4(uint32_t* r, uint32_t a) {
    asm volatile("ldmatrix.sync.aligned.m8n8.x4.shared.b16 {%0,%1,%2,%3}, [%4];"
        : "=r"(r[0]), "=r"(r[1]), "=r"(r[2]), "=r"(r[3]) : "r"(a));
}
__device__ __forceinline__ void mma_f16(float* d, const uint32_t* a, const uint32_t* b) {
    asm volatile("mma.sync.aligned.m16n8k16.row.col.f32.f16.f16.f32 "
        "{%0,%1,%2,%3}, {%4,%5,%6,%7}, {%8,%9}, {%0,%1,%2,%3};"
        : "+f"(d[0]), "+f"(d[1]), "+f"(d[2]), "+f"(d[3])
        : "r"(a[0]), "r"(a[1]), "r"(a[2]), "r"(a[3]), "r"(b[0]), "r"(b[1]));
}

// ---- prep: x -> swizzled fp16 channel-group planes (vectorized: 8 ch/thread) ----
__global__ __launch_bounds__(256) void cvt_x_k(const float* __restrict__ x) {
    int i = blockIdx.x * 256 + threadIdx.x;        // BS_*32 segs of 8 channels
    int R = i >> 5, s = i & 31;                    // s: 8-ch segment in row
    const float4* src = reinterpret_cast<const float4*>(x + (size_t)R * 256 + s * 8);
    float4 v0 = src[0], v1 = src[1];
    __half2 a = __floats2half2_rn(v0.x, v0.y), b = __floats2half2_rn(v0.z, v0.w);
    __half2 c = __floats2half2_rn(v1.x, v1.y), d = __floats2half2_rn(v1.z, v1.w);
    uint4 o = make_uint4(*(uint32_t*)&a, *(uint32_t*)&b, *(uint32_t*)&c, *(uint32_t*)&d);
    int cg = s >> 3, prow = R + 1;
    uint32_t byte = (uint32_t)((s & 7) << 4) ^ (uint32_t)((prow & 7) << 4);
    *reinterpret_cast<uint4*>(g_xa + (size_t)cg * PLANE_B + (size_t)prow * 128 + byte) = o;
}
// ---- prep: weights -> chunked+swizzled ----
__global__ __launch_bounds__(256) void cvt_w_k(const float* __restrict__ w1,
                                               const float* __restrict__ w2) {
    int gid = blockIdx.x * 256 + threadIdx.x;
    int ph = gid >= F_ * KK_;
    int idx = ph ? gid - F_ * KK_ : gid;
    int f = idx / 768, rem = idx - f * 768;
    int tap = rem >> 8, c = rem & 255;
    int kk = tap * 256 + c;
    int chunk = kk >> 6, kc = kk & 63;
    const float* w = ph ? w2 : w1;
    __half hv = __float2half(w[f * 768 + c * 3 + tap]);
    uint32_t byte = (uint32_t)(2 * kc) ^ (uint32_t)((f & 7) << 4);
    *reinterpret_cast<__half*>((ph ? g_w2s : g_w1s)
        + (size_t)chunk * W_TILE + (size_t)f * 128 + byte) = hv;
}

// ---- fused conv GEMM: M=64 tile, 8 warps, 2-stage TMA pipeline, 2 CTA/SM ----
template<int PH>
__global__ __launch_bounds__(256, 2) void conv_mma_k(
    const float* __restrict__ bias, const float* __restrict__ gam,
    const float* __restrict__ bet, const float* __restrict__ lw,
    const float* __restrict__ lbp, float* __restrict__ pred)
{
    extern __shared__ char smem[];
    const uint32_t sb0 = smem_u32(smem);
    const uint32_t tiles = (sb0 + 127) & ~127u;
    char* smc = smem + (tiles - sb0);
    float* sPar = (float*)(smc + OFF_PAR);
    float* sSum = (float*)(smc + OFF_SUM);
    float* sSq  = (float*)(smc + OFF_SQ);
    float* sLin = (float*)(smc + OFF_LIN);
    const uint32_t mb = tiles + OFF_MBAR;
    const int tid = threadIdx.x, lane = tid & 31, warp = tid >> 5;
    const int mw = warp >> 2, nw = warp & 3;       // 2x4 warps, warp tile 32x64
    const int mBase = blockIdx.x * 64;

    const char* Apl = PH ? g_h1a : g_xa;
    const char* Wst = PH ? g_w2s : g_w1s;

    sPar[tid] = bias[tid]; sPar[256 + tid] = gam[tid];
    sPar[512 + tid] = bet[tid]; sPar[768 + tid] = PH ? lw[tid] : 0.f;
    if (tid == 0) { MBAR_INIT(mb, 1); MBAR_INIT(mb + 8, 1); }
    __syncthreads();

    if (tid == 0) {
        #pragma unroll
        for (int j = 0; j < 2; j++) {              // prologue: chunks 0,1 (both taps=0)
            MBAR_EXPECT(mb + 8 * j, STG);
            bulk_cp(tiles + j * STG, Apl + (size_t)j * PLANE_B + (size_t)mBase * 128,
                    A_TILE, mb + 8 * j);
            bulk_cp(tiles + j * STG + A_TILE, Wst + (size_t)j * W_TILE, W_TILE, mb + 8 * j);
        }
    }

    float acc[2][8][4];
    #pragma unroll
    for (int a = 0; a < 2; a++)
        #pragma unroll
        for (int b = 0; b < 8; b++)
            #pragma unroll
            for (int c = 0; c < 4; c++) acc[a][b][c] = 0.f;

    int pha[2] = {0, 0};
    const bool fix0 = ((mBase & 511) == 0);        // tap0: first row from prev batch
    const bool fix2 = (((mBase + 64) & 511) == 0); // tap2: last row from next batch

    for (int i = 0; i < NCH; i++) {
        const int st = i & 1;
        const int tap = i >> 2;
        if (i >= 1) {
            __syncthreads();                        // drains chunk i-1 -> stage st^1 free
            if (tid == 0 && i + 1 < NCH) {
                const int nc = i + 1, ntap = nc >> 2, ncg = nc & 3;
                MBAR_EXPECT(mb + 8 * (st ^ 1), STG);
                bulk_cp(tiles + (st ^ 1) * STG,
                        Apl + (size_t)ncg * PLANE_B + (size_t)(mBase + ntap) * 128,
                        A_TILE, mb + 8 * (st ^ 1));
                bulk_cp(tiles + (st ^ 1) * STG + A_TILE, Wst + (size_t)nc * W_TILE,
                        W_TILE, mb + 8 * (st ^ 1));
            }
        }
        MBAR_WAIT(mb + 8 * st, pha[st]); pha[st] ^= 1;
        const uint32_t aT = tiles + st * STG, wT = aT + A_TILE;
        // 'same'-padding fixup at batch boundaries (reading warps, redundant-safe)
        if (tap == 0 && fix0 && mw == 0 && lane < 8)
            *reinterpret_cast<uint4*>(smc + st * STG + lane * 16) = make_uint4(0, 0, 0, 0);
        if (tap == 2 && fix2 && mw == 1 && lane < 8)
            *reinterpret_cast<uint4*>(smc + st * STG + 63 * 128 + lane * 16) = make_uint4(0, 0, 0, 0);
        __syncwarp();

        #pragma unroll
        for (int ks = 0; ks < 4; ks++) {
            uint32_t bf[8][2];
            #pragma unroll
            for (int njp = 0; njp < 4; njp++) {
                int f = nw * 64 + (2 * njp + ((lane >> 4) & 1)) * 8 + (lane & 7);
                int kseg = ks * 2 + ((lane >> 3) & 1);
                uint32_t ad = wT + (uint32_t)f * 128 + (uint32_t)((kseg ^ (f & 7)) << 4);
                uint32_t r[4];
                ldsm_x4(r, ad);
                bf[2 * njp][0] = r[0]; bf[2 * njp][1] = r[1];
                bf[2 * njp + 1][0] = r[2]; bf[2 * njp + 1][1] = r[3];
            }
            #pragma unroll
            for (int mi = 0; mi < 2; mi++) {
                int j = mw * 32 + mi * 16 + (lane & 7) + ((lane >> 3) & 1) * 8;
                int kseg = ks * 2 + ((lane >> 4) & 1);
                uint32_t ad = aT + (uint32_t)j * 128 + (uint32_t)((kseg ^ ((j + tap) & 7)) << 4);
                uint32_t af[4];
                ldsm_x4(af, ad);
                #pragma unroll
                for (int nj = 0; nj < 8; nj++)
                    mma_f16(acc[mi][nj], af, bf[nj]);
            }
        }
    }
    __syncthreads();

    // ---- epilogue: bias + LN partials ----
    #pragma unroll
    for (int mi = 0; mi < 2; mi++)
        #pragma unroll
        for (int rh = 0; rh < 2; rh++) {
            float s = 0.f, q = 0.f;
            #pragma unroll
            for (int nj = 0; nj < 8; nj++)
                #pragma unroll
                for (int h = 0; h < 2; h++) {
                    int col = nw * 64 + nj * 8 + 2 * (lane & 3) + h;
                    float v = acc[mi][nj][rh * 2 + h] + sPar[col];
                    acc[mi][nj][rh * 2 + h] = v;
                    s += v; q = fmaf(v, v, q);
                }
            s += __shfl_xor_sync(0xffffffffu, s, 1); s += __shfl_xor_sync(0xffffffffu, s, 2);
            q += __shfl_xor_sync(0xffffffffu, q, 1); q += __shfl_xor_sync(0xffffffffu, q, 2);
            if ((lane & 3) == 0) {
                int r = mw * 32 + mi * 16 + rh * 8 + (lane >> 2);
                sSum[nw * 64 + r] = s; sSq[nw * 64 + r] = q;
            }
        }
    __syncthreads();

    float lacc[2][2];
    #pragma unroll
    for (int mi = 0; mi < 2; mi++)
        #pragma unroll
        for (int rh = 0; rh < 2; rh++) {
            int r = mw * 32 + mi * 16 + rh * 8 + (lane >> 2);
            float tot = sSum[r] + sSum[64 + r] + sSum[128 + r] + sSum[192 + r];
            float tq  = sSq[r]  + sSq[64 + r]  + sSq[128 + r]  + sSq[192 + r];
            float mu = tot * (1.f / 256.f);
            float rstd = rsqrtf(tq * (1.f / 256.f) - mu * mu + 1e-5f);
            int rG = mBase + r;
            float la = 0.f;
            #pragma unroll
            for (int nj = 0; nj < 8; nj++) {
                int col0 = nw * 64 + nj * 8 + 2 * (lane & 3);
                float v0 = acc[mi][nj][rh * 2 + 0], v1 = acc[mi][nj][rh * 2 + 1];
                float o0 = fmaxf(0.f, fmaf((v0 - mu) * rstd, sPar[256 + col0],     sPar[512 + col0]));
                float o1 = fmaxf(0.f, fmaf((v1 - mu) * rstd, sPar[256 + col0 + 1], sPar[512 + col0 + 1]));
                if (PH == 0) {
                    __half2 hx = __floats2half2_rn(o0, o1);
                    int prow = rG + 1;
                    uint32_t byte = (uint32_t)(2 * (col0 & 63)) ^ (uint32_t)((prow & 7) << 4);
                    *reinterpret_cast<uint32_t*>(g_h1a + (size_t)nw * PLANE_B
                        + (size_t)prow * 128 + byte) = *reinterpret_cast<uint32_t*>(&hx);
                } else {
                    la = fmaf(o0, sPar[768 + col0], la);
                    la = fmaf(o1, sPar[768 + col0 + 1], la);
                }
            }
            lacc[mi][rh] = la;
        }

    if (PH == 1) {
        #pragma unroll
        for (int mi = 0; mi < 2; mi++)
            #pragma unroll
            for (int rh = 0; rh < 2; rh++) {
                float la = lacc[mi][rh];
                la += __shfl_xor_sync(0xffffffffu, la, 1);
                la += __shfl_xor_sync(0xffffffffu, la, 2);
                if ((lane & 3) == 0)
                    sLin[nw * 64 + mw * 32 + mi * 16 + rh * 8 + (lane >> 2)] = la;
            }
        __syncthreads();
        if (nw == 0 && (lane & 3) == 0) {
            #pragma unroll
            for (int mi = 0; mi < 2; mi++)
                #pragma unroll
                for (int rh = 0; rh < 2; rh++) {
                    int r = mw * 32 + mi * 16 + rh * 8 + (lane >> 2);
                    float t = sLin[r] + sLin[64 + r] + sLin[128 + r] + sLin[192 + r];
                    pred[mBase + r] = fmaxf(0.f, t + lbp[0]);
                }
        }
    }
}

// ---- rowmap + gather (unchanged, proven) ----
__global__ __launch_bounds__(512) void rowmap_k(const float* __restrict__ target, int L) {
    int b = blockIdx.x, s = threadIdx.x;
    int lane = s & 31, wp = s >> 5;
    int d = (int)rintf(target[b * 512 + s]);
    int v = d;
    #pragma unroll
    for (int o = 1; o < 32; o <<= 1) {
        int t = __shfl_up_sync(0xffffffffu, v, o);
        if (lane >= o) v += t;
    }
    __shared__ int wsum[16];
    if (lane == 31) wsum[wp] = v;
    __syncthreads();
    if (s < 16) {
        int w = wsum[s];
        #pragma unroll
        for (int o = 1; o < 16; o <<= 1) {
            int t = __shfl_up_sync(0x0000ffffu, w, o);
            if (s >= o) w += t;
        }
        wsum[s] = w;
    }
    __syncthreads();
    int end = v + (wp ? wsum[wp - 1] : 0);
    int start = end - d;
    int* rm = g_rowmap + (size_t)b * L;
    for (int l = s; l < L; l += 512) rm[l] = -1;
    __syncthreads();
    if (start < L) {
        int e = min(end, L);
        for (int l = start; l < e; ++l) rm[l] = s;
    }
}

__global__ __launch_bounds__(256) void gather_k(const float* __restrict__ x,
                                                float* __restrict__ out, int L) {
    int rowId = blockIdx.x * 4 + (threadIdx.x >> 6);
    if (rowId >= B_ * L) return;
    int t = threadIdx.x & 63;
    int b = rowId / L;
    int s = g_rowmap[rowId];
    float4 v = make_float4(0.f, 0.f, 0.f, 0.f);
    if (s >= 0)
        v = *reinterpret_cast<const float4*>(x + (size_t)((b << 9) + s) * D_ + (t << 2));
    *reinterpret_cast<float4*>(out + (size_t)rowId * D_ + (t << 2)) = v;
}

extern "C" void kernel_launch(void* const* d_in, const int* in_sizes, int n_in,
                              void* d_out, int out_size) {
    const float* x   = (const float*)d_in[0];
    const float* tgt = (const float*)d_in[1];
    const float* c1w = (const float*)d_in[2];
    const float* c1b = (const float*)d_in[3];
    const float* c2w = (const float*)d_in[4];
    const float* c2b = (const float*)d_in[5];
    const float* n1g = (const float*)d_in[6];
    const float* n1b = (const float*)d_in[7];
    const float* n2g = (const float*)d_in[8];
    const float* n2b = (const float*)d_in[9];
    const float* lw  = (const float*)d_in[10];
    const float* lb  = (const float*)d_in[11];

    float* out = (float*)d_out;
    int L = (out_size - B_ * S_) / (B_ * D_);
    float* pred = out + (size_t)B_ * L * D_;

    static cudaStream_t s2 = nullptr;
    static cudaEvent_t evF = nullptr, evJ = nullptr;
    if (s2 == nullptr) {
        cudaStreamCreateWithFlags(&s2, cudaStreamNonBlocking);
        cudaEventCreateWithFlags(&evF, cudaEventDisableTiming);
        cudaEventCreateWithFlags(&evJ, cudaEventDisableTiming);
        cudaFuncSetAttribute(conv_mma_k<0>, cudaFuncAttributeMaxDynamicSharedMemorySize, SMEM_TOTAL);
        cudaFuncSetAttribute(conv_mma_k<1>, cudaFuncAttributeMaxDynamicSharedMemorySize, SMEM_TOTAL);
    }

    // fork: length-regulator branch overlaps the conv branch
    cudaEventRecord(evF, 0);
    cudaStreamWaitEvent(s2, evF, 0);
    rowmap_k<<<B_, 512, 0, s2>>>(tgt, L);
    gather_k<<<(B_ * L + 3) / 4, 256, 0, s2>>>(x, out, L);
    cudaEventRecord(evJ, s2);

    // main: duration-predictor branch
    cvt_w_k<<<2 * F_ * KK_ / 256, 256>>>(c1w, c2w);
    cvt_x_k<<<BS_ * 32 / 256, 256>>>(x);
    conv_mma_k<0><<<256, 256, SMEM_TOTAL>>>(c1b, n1g, n1b, lw, lb, pred);
    conv_mma_k<1><<<256, 256, SMEM_TOTAL>>>(c2b, n2g, n2b, lw, lb, pred);

    // join
    cudaStreamWaitEvent(0, evJ, 0);
}

// round 10
// speedup vs baseline: 6.3417x; 1.1336x over previous
#include <cuda_runtime.h>
#include <cuda_fp16.h>
#include <cstdint>

#define B_  32
#define S_  512
#define D_  256
#define F_  256
#define BS_ 16384
#define KK_ 768
#define NCH 12
#define PLANE_ROWS 16386
#define PLANE_B (PLANE_ROWS*128)
#define A_TILE 8192                // 64 rows x 128B, pre-swizzled
#define W_TILE 32768               // 256 rows x 128B
#define STG (A_TILE + W_TILE)      // 40960
#define OFF_PAR (2*STG)            // 81920
#define OFF_SUM (OFF_PAR + 4096)
#define OFF_SQ  (OFF_SUM + 1024)
#define OFF_LIN (OFF_SQ  + 1024)
#define OFF_MBAR (OFF_LIN + 1024)
#define SMEM_TOTAL (OFF_MBAR + 64 + 128)   // ~89.3KB -> 2 CTAs/SM

__device__ char g_xa [4*PLANE_B];
__device__ char g_h1a[4*PLANE_B];
__device__ char g_w1s[NCH*W_TILE];
__device__ char g_w2s[NCH*W_TILE];
__device__ int  g_rowmap[B_*4608];

__device__ __forceinline__ uint32_t smem_u32(const void* p) {
    uint32_t a;
    asm("{ .reg .u64 t; cvta.to.shared.u64 t, %1; cvt.u32.u64 %0, t; }" : "=r"(a) : "l"(p));
    return a;
}
#define MBAR_INIT(a, c) asm volatile("mbarrier.init.shared.b64 [%0], %1;" :: "r"((uint32_t)(a)), "r"((uint32_t)(c)) : "memory")
#define MBAR_EXPECT(a, b) asm volatile("mbarrier.arrive.expect_tx.shared.b64 _, [%0], %1;" :: "r"((uint32_t)(a)), "r"((uint32_t)(b)) : "memory")
#define MBAR_ARRIVE(a) asm volatile("mbarrier.arrive.shared.b64 _, [%0];" :: "r"((uint32_t)(a)) : "memory")
#define MBAR_WAIT(a, ph) do { \
    uint32_t _m = (uint32_t)(a), _p = (uint32_t)(ph), _d; \
    asm volatile("{ .reg .pred p; mbarrier.try_wait.parity.acquire.cta.shared::cta.b64 p, [%1], %2; selp.b32 %0, 1, 0, p; }" \
        : "=r"(_d) : "r"(_m), "r"(_p) : "memory"); \
    if (!_d) { asm volatile("{ .reg .pred P1;\nWL_%=:\n" \
        "mbarrier.try_wait.parity.acquire.cta.shared::cta.b64 P1, [%0], %1, 0x989680;\n" \
        "@P1 bra.uni WD_%=;\nbra.uni WL_%=;\nWD_%=:\n}" :: "r"(_m), "r"(_p) : "memory"); } \
} while (0)
__device__ __forceinline__ void bulk_cp(uint32_t dst, const void* src, uint32_t bytes, uint32_t mbar) {
    asm volatile("cp.async.bulk.shared::cta.global.mbarrier::complete_tx::bytes [%0], [%1], %2, [%3];"
        :: "r"(dst), "l"(src), "r"(bytes), "r"(mbar) : "memory");
}
__device__ __forceinline__ void ldsm_x4(uint32_t* r, uint32_t a) {
    asm volatile("ldmatrix.sync.aligned.m8n8.x4.shared.b16 {%0,%1,%2,%3}, [%4];"
        : "=r"(r[0]), "=r"(r[1]), "=r"(r[2]), "=r"(r[3]) : "r"(a));
}
__device__ __forceinline__ void mma_f16(float* d, const uint32_t* a, const uint32_t* b) {
    asm volatile("mma.sync.aligned.m16n8k16.row.col.f32.f16.f16.f32 "
        "{%0,%1,%2,%3}, {%4,%5,%6,%7}, {%8,%9}, {%0,%1,%2,%3};"
        : "+f"(d[0]), "+f"(d[1]), "+f"(d[2]), "+f"(d[3])
        : "r"(a[0]), "r"(a[1]), "r"(a[2]), "r"(a[3]), "r"(b[0]), "r"(b[1]));
}

// ---- prep: x -> swizzled fp16 channel-group planes (8 ch/thread) ----
__global__ __launch_bounds__(256) void cvt_x_k(const float* __restrict__ x) {
    int i = blockIdx.x * 256 + threadIdx.x;
    int R = i >> 5, s = i & 31;
    const float4* src = reinterpret_cast<const float4*>(x + (size_t)R * 256 + s * 8);
    float4 v0 = src[0], v1 = src[1];
    __half2 a = __floats2half2_rn(v0.x, v0.y), b = __floats2half2_rn(v0.z, v0.w);
    __half2 c = __floats2half2_rn(v1.x, v1.y), d = __floats2half2_rn(v1.z, v1.w);
    uint4 o = make_uint4(*(uint32_t*)&a, *(uint32_t*)&b, *(uint32_t*)&c, *(uint32_t*)&d);
    int cg = s >> 3, prow = R + 1;
    uint32_t byte = (uint32_t)((s & 7) << 4) ^ (uint32_t)((prow & 7) << 4);
    *reinterpret_cast<uint4*>(g_xa + (size_t)cg * PLANE_B + (size_t)prow * 128 + byte) = o;
}
// ---- prep: weights -> chunked+swizzled ----
__global__ __launch_bounds__(256) void cvt_w_k(const float* __restrict__ w1,
                                               const float* __restrict__ w2) {
    int gid = blockIdx.x * 256 + threadIdx.x;
    int ph = gid >= F_ * KK_;
    int idx = ph ? gid - F_ * KK_ : gid;
    int f = idx / 768, rem = idx - f * 768;
    int tap = rem >> 8, c = rem & 255;
    int kk = tap * 256 + c;
    int chunk = kk >> 6, kc = kk & 63;
    const float* w = ph ? w2 : w1;
    __half hv = __float2half(w[f * 768 + c * 3 + tap]);
    uint32_t byte = (uint32_t)(2 * kc) ^ (uint32_t)((f & 7) << 4);
    *reinterpret_cast<__half*>((ph ? g_w2s : g_w1s)
        + (size_t)chunk * W_TILE + (size_t)f * 128 + byte) = hv;
}

// ---- fused conv GEMM: M=64, 8 warps, 2-stage ring, producer-consumer mbarriers ----
template<int PH>
__global__ __launch_bounds__(256, 2) void conv_mma_k(
    const float* __restrict__ bias, const float* __restrict__ gam,
    const float* __restrict__ bet, const float* __restrict__ lw,
    const float* __restrict__ lbp, float* __restrict__ pred)
{
    extern __shared__ char smem[];
    const uint32_t sb0 = smem_u32(smem);
    const uint32_t tiles = (sb0 + 127) & ~127u;
    char* smc = smem + (tiles - sb0);
    float* sPar = (float*)(smc + OFF_PAR);
    float* sSum = (float*)(smc + OFF_SUM);
    float* sSq  = (float*)(smc + OFF_SQ);
    float* sLin = (float*)(smc + OFF_LIN);
    const uint32_t mbF = tiles + OFF_MBAR;        // full[0], full[1]
    const uint32_t mbE = mbF + 16;                // empty[0], empty[1]
    const int tid = threadIdx.x, lane = tid & 31, warp = tid >> 5;
    const int mw = warp >> 2, nw = warp & 3;
    const int mBase = blockIdx.x * 64;

    const char* Apl = PH ? g_h1a : g_xa;
    const char* Wst = PH ? g_w2s : g_w1s;

    sPar[tid] = bias[tid]; sPar[256 + tid] = gam[tid];
    sPar[512 + tid] = bet[tid]; sPar[768 + tid] = PH ? lw[tid] : 0.f;
    if (tid == 0) {
        MBAR_INIT(mbF, 1); MBAR_INIT(mbF + 8, 1);
        MBAR_INIT(mbE, 8); MBAR_INIT(mbE + 8, 8);
    }
    __syncthreads();

    if (tid == 0) {
        #pragma unroll
        for (int j = 0; j < 2; j++) {              // prologue: chunks 0,1 (tap 0)
            MBAR_EXPECT(mbF + 8 * j, STG);
            bulk_cp(tiles + j * STG, Apl + (size_t)j * PLANE_B + (size_t)mBase * 128,
                    A_TILE, mbF + 8 * j);
            bulk_cp(tiles + j * STG + A_TILE, Wst + (size_t)j * W_TILE, W_TILE, mbF + 8 * j);
        }
    }

    float acc[2][8][4];
    #pragma unroll
    for (int a = 0; a < 2; a++)
        #pragma unroll
        for (int b = 0; b < 8; b++)
            #pragma unroll
            for (int c = 0; c < 4; c++) acc[a][b][c] = 0.f;

    int pha[2] = {0, 0};                           // full phases (consumer)
    int eph[2] = {0, 0};                           // empty phases (producer)
    const bool fix0 = ((mBase & 511) == 0);
    const bool fix2 = (((mBase + 64) & 511) == 0);

    for (int i = 0; i < NCH; i++) {
        const int st = i & 1;
        const int tap = i >> 2;
        // producer (thread 0): refill stage st^1 once chunk i-1's consumers are done
        if (tid == 0 && i >= 1 && i + 1 < NCH) {
            const int st2 = st ^ 1;
            MBAR_WAIT(mbE + 8 * st2, eph[st2]); eph[st2] ^= 1;
            const int nc = i + 1, ntap = nc >> 2, ncg = nc & 3;
            MBAR_EXPECT(mbF + 8 * st2, STG);
            bulk_cp(tiles + st2 * STG,
                    Apl + (size_t)ncg * PLANE_B + (size_t)(mBase + ntap) * 128,
                    A_TILE, mbF + 8 * st2);
            bulk_cp(tiles + st2 * STG + A_TILE, Wst + (size_t)nc * W_TILE,
                    W_TILE, mbF + 8 * st2);
        }
        MBAR_WAIT(mbF + 8 * st, pha[st]); pha[st] ^= 1;
        const uint32_t aT = tiles + st * STG, wT = aT + A_TILE;
        // 'same'-padding fixup (per reading warp, redundant-safe)
        if (tap == 0 && fix0 && mw == 0 && lane < 8)
            *reinterpret_cast<uint4*>(smc + st * STG + lane * 16) = make_uint4(0, 0, 0, 0);
        if (tap == 2 && fix2 && mw == 1 && lane < 8)
            *reinterpret_cast<uint4*>(smc + st * STG + 63 * 128 + lane * 16) = make_uint4(0, 0, 0, 0);
        __syncwarp();

        #pragma unroll
        for (int ks = 0; ks < 4; ks++) {
            uint32_t bf[8][2];
            #pragma unroll
            for (int njp = 0; njp < 4; njp++) {
                int f = nw * 64 + (2 * njp + ((lane >> 4) & 1)) * 8 + (lane & 7);
                int kseg = ks * 2 + ((lane >> 3) & 1);
                uint32_t ad = wT + (uint32_t)f * 128 + (uint32_t)((kseg ^ (f & 7)) << 4);
                uint32_t r[4];
                ldsm_x4(r, ad);
                bf[2 * njp][0] = r[0]; bf[2 * njp][1] = r[1];
                bf[2 * njp + 1][0] = r[2]; bf[2 * njp + 1][1] = r[3];
            }
            #pragma unroll
            for (int mi = 0; mi < 2; mi++) {
                int j = mw * 32 + mi * 16 + (lane & 7) + ((lane >> 3) & 1) * 8;
                int kseg = ks * 2 + ((lane >> 4) & 1);
                uint32_t ad = aT + (uint32_t)j * 128 + (uint32_t)((kseg ^ ((j + tap) & 7)) << 4);
                uint32_t af[4];
                ldsm_x4(af, ad);
                #pragma unroll
                for (int nj = 0; nj < 8; nj++)
                    mma_f16(acc[mi][nj], af, bf[nj]);
            }
        }
        if (lane == 0) MBAR_ARRIVE(mbE + 8 * st);   // this warp is done with stage st
    }
    __syncthreads();

    // ---- epilogue: bias + LN partials ----
    #pragma unroll
    for (int mi = 0; mi < 2; mi++)
        #pragma unroll
        for (int rh = 0; rh < 2; rh++) {
            float s = 0.f, q = 0.f;
            #pragma unroll
            for (int nj = 0; nj < 8; nj++)
                #pragma unroll
                for (int h = 0; h < 2; h++) {
                    int col = nw * 64 + nj * 8 + 2 * (lane & 3) + h;
                    float v = acc[mi][nj][rh * 2 + h] + sPar[col];
                    acc[mi][nj][rh * 2 + h] = v;
                    s += v; q = fmaf(v, v, q);
                }
            s += __shfl_xor_sync(0xffffffffu, s, 1); s += __shfl_xor_sync(0xffffffffu, s, 2);
            q += __shfl_xor_sync(0xffffffffu, q, 1); q += __shfl_xor_sync(0xffffffffu, q, 2);
            if ((lane & 3) == 0) {
                int r = mw * 32 + mi * 16 + rh * 8 + (lane >> 2);
                sSum[nw * 64 + r] = s; sSq[nw * 64 + r] = q;
            }
        }
    __syncthreads();

    float lacc[2][2];
    #pragma unroll
    for (int mi = 0; mi < 2; mi++)
        #pragma unroll
        for (int rh = 0; rh < 2; rh++) {
            int r = mw * 32 + mi * 16 + rh * 8 + (lane >> 2);
            float tot = sSum[r] + sSum[64 + r] + sSum[128 + r] + sSum[192 + r];
            float tq  = sSq[r]  + sSq[64 + r]  + sSq[128 + r]  + sSq[192 + r];
            float mu = tot * (1.f / 256.f);
            float rstd = rsqrtf(tq * (1.f / 256.f) - mu * mu + 1e-5f);
            int rG = mBase + r;
            float la = 0.f;
            #pragma unroll
            for (int nj = 0; nj < 8; nj++) {
                int col0 = nw * 64 + nj * 8 + 2 * (lane & 3);
                float v0 = acc[mi][nj][rh * 2 + 0], v1 = acc[mi][nj][rh * 2 + 1];
                float o0 = fmaxf(0.f, fmaf((v0 - mu) * rstd, sPar[256 + col0],     sPar[512 + col0]));
                float o1 = fmaxf(0.f, fmaf((v1 - mu) * rstd, sPar[256 + col0 + 1], sPar[512 + col0 + 1]));
                if (PH == 0) {
                    __half2 hx = __floats2half2_rn(o0, o1);
                    int prow = rG + 1;
                    uint32_t byte = (uint32_t)(2 * (col0 & 63)) ^ (uint32_t)((prow & 7) << 4);
                    *reinterpret_cast<uint32_t*>(g_h1a + (size_t)nw * PLANE_B
                        + (size_t)prow * 128 + byte) = *reinterpret_cast<uint32_t*>(&hx);
                } else {
                    la = fmaf(o0, sPar[768 + col0], la);
                    la = fmaf(o1, sPar[768 + col0 + 1], la);
                }
            }
            lacc[mi][rh] = la;
        }

    if (PH == 1) {
        #pragma unroll
        for (int mi = 0; mi < 2; mi++)
            #pragma unroll
            for (int rh = 0; rh < 2; rh++) {
                float la = lacc[mi][rh];
                la += __shfl_xor_sync(0xffffffffu, la, 1);
                la += __shfl_xor_sync(0xffffffffu, la, 2);
                if ((lane & 3) == 0)
                    sLin[nw * 64 + mw * 32 + mi * 16 + rh * 8 + (lane >> 2)] = la;
            }
        __syncthreads();
        if (nw == 0 && (lane & 3) == 0) {
            #pragma unroll
            for (int mi = 0; mi < 2; mi++)
                #pragma unroll
                for (int rh = 0; rh < 2; rh++) {
                    int r = mw * 32 + mi * 16 + rh * 8 + (lane >> 2);
                    float t = sLin[r] + sLin[64 + r] + sLin[128 + r] + sLin[192 + r];
                    pred[mBase + r] = fmaxf(0.f, t + lbp[0]);
                }
        }
    }
}

// ---- rowmap + gather (unchanged, proven) ----
__global__ __launch_bounds__(512) void rowmap_k(const float* __restrict__ target, int L) {
    int b = blockIdx.x, s = threadIdx.x;
    int lane = s & 31, wp = s >> 5;
    int d = (int)rintf(target[b * 512 + s]);
    int v = d;
    #pragma unroll
    for (int o = 1; o < 32; o <<= 1) {
        int t = __shfl_up_sync(0xffffffffu, v, o);
        if (lane >= o) v += t;
    }
    __shared__ int wsum[16];
    if (lane == 31) wsum[wp] = v;
    __syncthreads();
    if (s < 16) {
        int w = wsum[s];
        #pragma unroll
        for (int o = 1; o < 16; o <<= 1) {
            int t = __shfl_up_sync(0x0000ffffu, w, o);
            if (s >= o) w += t;
        }
        wsum[s] = w;
    }
    __syncthreads();
    int end = v + (wp ? wsum[wp - 1] : 0);
    int start = end - d;
    int* rm = g_rowmap + (size_t)b * L;
    for (int l = s; l < L; l += 512) rm[l] = -1;
    __syncthreads();
    if (start < L) {
        int e = min(end, L);
        for (int l = start; l < e; ++l) rm[l] = s;
    }
}

__global__ __launch_bounds__(256) void gather_k(const float* __restrict__ x,
                                                float* __restrict__ out, int L) {
    int rowId = blockIdx.x * 4 + (threadIdx.x >> 6);
    if (rowId >= B_ * L) return;
    int t = threadIdx.x & 63;
    int b = rowId / L;
    int s = g_rowmap[rowId];
    float4 v = make_float4(0.f, 0.f, 0.f, 0.f);
    if (s >= 0)
        v = *reinterpret_cast<const float4*>(x + (size_t)((b << 9) + s) * D_ + (t << 2));
    *reinterpret_cast<float4*>(out + (size_t)rowId * D_ + (t << 2)) = v;
}

extern "C" void kernel_launch(void* const* d_in, const int* in_sizes, int n_in,
                              void* d_out, int out_size) {
    const float* x   = (const float*)d_in[0];
    const float* tgt = (const float*)d_in[1];
    const float* c1w = (const float*)d_in[2];
    const float* c1b = (const float*)d_in[3];
    const float* c2w = (const float*)d_in[4];
    const float* c2b = (const float*)d_in[5];
    const float* n1g = (const float*)d_in[6];
    const float* n1b = (const float*)d_in[7];
    const float* n2g = (const float*)d_in[8];
    const float* n2b = (const float*)d_in[9];
    const float* lw  = (const float*)d_in[10];
    const float* lb  = (const float*)d_in[11];

    float* out = (float*)d_out;
    int L = (out_size - B_ * S_) / (B_ * D_);
    float* pred = out + (size_t)B_ * L * D_;

    static cudaStream_t sHi = nullptr, sLo = nullptr;
    static cudaEvent_t evF = nullptr, evW = nullptr, evH = nullptr, evJ = nullptr;
    if (sHi == nullptr) {
        int pLo, pHi;
        cudaDeviceGetStreamPriorityRange(&pLo, &pHi);
        cudaStreamCreateWithPriority(&sHi, cudaStreamNonBlocking, pHi);
        cudaStreamCreateWithPriority(&sLo, cudaStreamNonBlocking, pLo);
        cudaEventCreateWithFlags(&evF, cudaEventDisableTiming);
        cudaEventCreateWithFlags(&evW, cudaEventDisableTiming);
        cudaEventCreateWithFlags(&evH, cudaEventDisableTiming);
        cudaEventCreateWithFlags(&evJ, cudaEventDisableTiming);
        cudaFuncSetAttribute(conv_mma_k<0>, cudaFuncAttributeMaxDynamicSharedMemorySize, SMEM_TOTAL);
        cudaFuncSetAttribute(conv_mma_k<1>, cudaFuncAttributeMaxDynamicSharedMemorySize, SMEM_TOTAL);
    }

    // fork
    cudaEventRecord(evF, 0);
    cudaStreamWaitEvent(sHi, evF, 0);
    cudaStreamWaitEvent(sLo, evF, 0);

    // low-priority branch: weight prep + length regulator
    cvt_w_k<<<2 * F_ * KK_ / 256, 256, 0, sLo>>>(c1w, c2w);
    cudaEventRecord(evW, sLo);
    rowmap_k<<<B_, 512, 0, sLo>>>(tgt, L);
    gather_k<<<(B_ * L + 3) / 4, 256, 0, sLo>>>(x, out, L);
    cudaEventRecord(evJ, sLo);

    // high-priority branch: duration predictor
    cvt_x_k<<<BS_ * 32 / 256, 256, 0, sHi>>>(x);
    cudaStreamWaitEvent(sHi, evW, 0);
    conv_mma_k<0><<<256, 256, SMEM_TOTAL, sHi>>>(c1b, n1g, n1b, lw, lb, pred);
    conv_mma_k<1><<<256, 256, SMEM_TOTAL, sHi>>>(c2b, n2g, n2b, lw, lb, pred);
    cudaEventRecord(evH, sHi);

    // join
    cudaStreamWaitEvent(0, evH, 0);
    cudaStreamWaitEvent(0, evJ, 0);
}

// round 11
// speedup vs baseline: 6.8052x; 1.0731x over previous
#include <cuda_runtime.h>
#include <cuda_fp16.h>
#include <cstdint>

#define B_  32
#define S_  512
#define D_  256
#define F_  256
#define BS_ 16384
#define KK_ 768
#define NCH 12
#define PLANE_ROWS 16386
#define PLANE_B (PLANE_ROWS*128)
#define A_TILE 8192
#define W_TILE 32768
#define STG (A_TILE + W_TILE)      // 40960
#define OFF_PAR (2*STG)            // 81920 (2 phases x 1024 floats)
#define OFF_SUM (OFF_PAR + 8192)
#define OFF_SQ  (OFF_SUM + 1024)
#define OFF_LIN (OFF_SQ  + 1024)
#define OFF_MBAR (OFF_LIN + 1024)
#define SMEM_TOTAL (OFF_MBAR + 64 + 128)   // ~91.3KB -> 2 CTAs/SM

__device__ char g_xa [4*PLANE_B];
__device__ char g_h1a[4*PLANE_B];
__device__ char g_w1s[NCH*W_TILE];
__device__ char g_w2s[NCH*W_TILE];
__device__ int  g_rowmap[B_*4608];
__device__ int  g_flag[256];               // monotonic per-launch counters

__device__ __forceinline__ uint32_t smem_u32(const void* p) {
    uint32_t a;
    asm("{ .reg .u64 t; cvta.to.shared.u64 t, %1; cvt.u32.u64 %0, t; }" : "=r"(a) : "l"(p));
    return a;
}
#define MBAR_INIT(a, c) asm volatile("mbarrier.init.shared.b64 [%0], %1;" :: "r"((uint32_t)(a)), "r"((uint32_t)(c)) : "memory")
#define MBAR_EXPECT(a, b) asm volatile("mbarrier.arrive.expect_tx.shared.b64 _, [%0], %1;" :: "r"((uint32_t)(a)), "r"((uint32_t)(b)) : "memory")
#define MBAR_ARRIVE(a) asm volatile("mbarrier.arrive.shared.b64 _, [%0];" :: "r"((uint32_t)(a)) : "memory")
#define MBAR_WAIT(a, ph) do { \
    uint32_t _m = (uint32_t)(a), _p = (uint32_t)(ph), _d; \
    asm volatile("{ .reg .pred p; mbarrier.try_wait.parity.acquire.cta.shared::cta.b64 p, [%1], %2; selp.b32 %0, 1, 0, p; }" \
        : "=r"(_d) : "r"(_m), "r"(_p) : "memory"); \
    if (!_d) { asm volatile("{ .reg .pred P1;\nWL_%=:\n" \
        "mbarrier.try_wait.parity.acquire.cta.shared::cta.b64 P1, [%0], %1, 0x989680;\n" \
        "@P1 bra.uni WD_%=;\nbra.uni WL_%=;\nWD_%=:\n}" :: "r"(_m), "r"(_p) : "memory"); } \
} while (0)
__device__ __forceinline__ void bulk_cp(uint32_t dst, const void* src, uint32_t bytes, uint32_t mbar) {
    asm volatile("cp.async.bulk.shared::cta.global.mbarrier::complete_tx::bytes [%0], [%1], %2, [%3];"
        :: "r"(dst), "l"(src), "r"(bytes), "r"(mbar) : "memory");
}
__device__ __forceinline__ void ldsm_x4(uint32_t* r, uint32_t a) {
    asm volatile("ldmatrix.sync.aligned.m8n8.x4.shared.b16 {%0,%1,%2,%3}, [%4];"
        : "=r"(r[0]), "=r"(r[1]), "=r"(r[2]), "=r"(r[3]) : "r"(a));
}
__device__ __forceinline__ void mma_f16(float* d, const uint32_t* a, const uint32_t* b) {
    asm volatile("mma.sync.aligned.m16n8k16.row.col.f32.f16.f16.f32 "
        "{%0,%1,%2,%3}, {%4,%5,%6,%7}, {%8,%9}, {%0,%1,%2,%3};"
        : "+f"(d[0]), "+f"(d[1]), "+f"(d[2]), "+f"(d[3])
        : "r"(a[0]), "r"(a[1]), "r"(a[2]), "r"(a[3]), "r"(b[0]), "r"(b[1]));
}
__device__ __forceinline__ int ld_acq(const int* p) {
    int v; asm volatile("ld.acquire.gpu.global.s32 %0, [%1];" : "=r"(v) : "l"(p)); return v;
}

// ---- prep: x -> swizzled fp16 channel-group planes (2 segs/thread for ILP) ----
__global__ __launch_bounds__(256) void cvt_x_k(const float* __restrict__ x) {
    int i0 = blockIdx.x * 256 + threadIdx.x;
    #pragma unroll
    for (int h = 0; h < 2; h++) {
        int i = i0 + h * (BS_ * 16);
        int R = i >> 5, s = i & 31;
        const float4* src = reinterpret_cast<const float4*>(x + (size_t)R * 256 + s * 8);
        float4 v0 = src[0], v1 = src[1];
        __half2 a = __floats2half2_rn(v0.x, v0.y), b = __floats2half2_rn(v0.z, v0.w);
        __half2 c = __floats2half2_rn(v1.x, v1.y), d = __floats2half2_rn(v1.z, v1.w);
        uint4 o = make_uint4(*(uint32_t*)&a, *(uint32_t*)&b, *(uint32_t*)&c, *(uint32_t*)&d);
        int cg = s >> 3, prow = R + 1;
        uint32_t byte = (uint32_t)((s & 7) << 4) ^ (uint32_t)((prow & 7) << 4);
        *reinterpret_cast<uint4*>(g_xa + (size_t)cg * PLANE_B + (size_t)prow * 128 + byte) = o;
    }
}
// ---- prep: weights -> chunked+swizzled ----
__global__ __launch_bounds__(256) void cvt_w_k(const float* __restrict__ w1,
                                               const float* __restrict__ w2) {
    int gid = blockIdx.x * 256 + threadIdx.x;
    int ph = gid >= F_ * KK_;
    int idx = ph ? gid - F_ * KK_ : gid;
    int f = idx / 768, rem = idx - f * 768;
    int tap = rem >> 8, c = rem & 255;
    int kk = tap * 256 + c;
    int chunk = kk >> 6, kc = kk & 63;
    const float* w = ph ? w2 : w1;
    __half hv = __float2half(w[f * 768 + c * 3 + tap]);
    uint32_t byte = (uint32_t)(2 * kc) ^ (uint32_t)((f & 7) << 4);
    *reinterpret_cast<__half*>((ph ? g_w2s : g_w1s)
        + (size_t)chunk * W_TILE + (size_t)f * 128 + byte) = hv;
}

// ---- one conv phase: main loop + epilogue; PH=0 writes h1a, PH=1 writes pred ----
template<int PH>
__device__ __forceinline__ void conv_phase(
    char* smc, uint32_t tiles, const char* Apl, const char* Wst,
    int mBase, int tid, int lane, int mw, int nw,
    int* pha, int* eph, const float* par,
    float* sSum, float* sSq, float* sLin,
    float* pred, const float* lbp, bool skipPrologue)
{
    const uint32_t mbF = tiles + OFF_MBAR, mbE = mbF + 16;
    if (!skipPrologue && tid == 0) {
        #pragma unroll
        for (int j = 0; j < 2; j++) {
            MBAR_EXPECT(mbF + 8 * j, STG);
            bulk_cp(tiles + j * STG, Apl + (size_t)j * PLANE_B + (size_t)mBase * 128,
                    A_TILE, mbF + 8 * j);
            bulk_cp(tiles + j * STG + A_TILE, Wst + (size_t)j * W_TILE, W_TILE, mbF + 8 * j);
        }
    }
    float acc[2][8][4];
    #pragma unroll
    for (int a = 0; a < 2; a++)
        #pragma unroll
        for (int b = 0; b < 8; b++)
            #pragma unroll
            for (int c = 0; c < 4; c++) acc[a][b][c] = 0.f;

    const bool fix0 = ((mBase & 511) == 0);
    const bool fix2 = (((mBase + 64) & 511) == 0);

    for (int i = 0; i < NCH; i++) {
        const int st = i & 1;
        const int tap = i >> 2;
        if (tid == 0 && i >= 1 && i + 1 < NCH) {
            const int st2 = st ^ 1;
            MBAR_WAIT(mbE + 8 * st2, eph[st2]); eph[st2] ^= 1;
            const int nc = i + 1, ntap = nc >> 2, ncg = nc & 3;
            MBAR_EXPECT(mbF + 8 * st2, STG);
            bulk_cp(tiles + st2 * STG,
                    Apl + (size_t)ncg * PLANE_B + (size_t)(mBase + ntap) * 128,
                    A_TILE, mbF + 8 * st2);
            bulk_cp(tiles + st2 * STG + A_TILE, Wst + (size_t)nc * W_TILE,
                    W_TILE, mbF + 8 * st2);
        }
        MBAR_WAIT(mbF + 8 * st, pha[st]); pha[st] ^= 1;
        const uint32_t aT = tiles + st * STG, wT = aT + A_TILE;
        if (tap == 0 && fix0 && mw == 0 && lane < 8)
            *reinterpret_cast<uint4*>(smc + st * STG + lane * 16) = make_uint4(0, 0, 0, 0);
        if (tap == 2 && fix2 && mw == 1 && lane < 8)
            *reinterpret_cast<uint4*>(smc + st * STG + 63 * 128 + lane * 16) = make_uint4(0, 0, 0, 0);
        __syncwarp();

        #pragma unroll
        for (int ks = 0; ks < 4; ks++) {
            uint32_t bf[8][2];
            #pragma unroll
            for (int njp = 0; njp < 4; njp++) {
                int f = nw * 64 + (2 * njp + ((lane >> 4) & 1)) * 8 + (lane & 7);
                int kseg = ks * 2 + ((lane >> 3) & 1);
                uint32_t ad = wT + (uint32_t)f * 128 + (uint32_t)((kseg ^ (f & 7)) << 4);
                uint32_t r[4];
                ldsm_x4(r, ad);
                bf[2 * njp][0] = r[0]; bf[2 * njp][1] = r[1];
                bf[2 * njp + 1][0] = r[2]; bf[2 * njp + 1][1] = r[3];
            }
            #pragma unroll
            for (int mi = 0; mi < 2; mi++) {
                int j = mw * 32 + mi * 16 + (lane & 7) + ((lane >> 3) & 1) * 8;
                int kseg = ks * 2 + ((lane >> 4) & 1);
                uint32_t ad = aT + (uint32_t)j * 128 + (uint32_t)((kseg ^ ((j + tap) & 7)) << 4);
                uint32_t af[4];
                ldsm_x4(af, ad);
                #pragma unroll
                for (int nj = 0; nj < 8; nj++)
                    mma_f16(acc[mi][nj], af, bf[nj]);
            }
        }
        if (lane == 0) MBAR_ARRIVE(mbE + 8 * st);
    }
    __syncthreads();

    // ---- between-loop hook for PH=0: consume leftover empties + prefetch W2 ----
    if (PH == 0 && tid == 0) {
        MBAR_WAIT(mbE, eph[0]); eph[0] ^= 1;
        MBAR_WAIT(mbE + 8, eph[1]); eph[1] ^= 1;
        #pragma unroll
        for (int j = 0; j < 2; j++) {
            MBAR_EXPECT(mbF + 8 * j, STG);
            bulk_cp(tiles + j * STG + A_TILE, g_w2s + (size_t)j * W_TILE, W_TILE, mbF + 8 * j);
        }
    }

    // ---- epilogue: bias + LN ----
    #pragma unroll
    for (int mi = 0; mi < 2; mi++)
        #pragma unroll
        for (int rh = 0; rh < 2; rh++) {
            float s = 0.f, q = 0.f;
            #pragma unroll
            for (int nj = 0; nj < 8; nj++)
                #pragma unroll
                for (int h = 0; h < 2; h++) {
                    int col = nw * 64 + nj * 8 + 2 * (lane & 3) + h;
                    float v = acc[mi][nj][rh * 2 + h] + par[col];
                    acc[mi][nj][rh * 2 + h] = v;
                    s += v; q = fmaf(v, v, q);
                }
            s += __shfl_xor_sync(0xffffffffu, s, 1); s += __shfl_xor_sync(0xffffffffu, s, 2);
            q += __shfl_xor_sync(0xffffffffu, q, 1); q += __shfl_xor_sync(0xffffffffu, q, 2);
            if ((lane & 3) == 0) {
                int r = mw * 32 + mi * 16 + rh * 8 + (lane >> 2);
                sSum[nw * 64 + r] = s; sSq[nw * 64 + r] = q;
            }
        }
    __syncthreads();

    float lacc[2][2];
    #pragma unroll
    for (int mi = 0; mi < 2; mi++)
        #pragma unroll
        for (int rh = 0; rh < 2; rh++) {
            int r = mw * 32 + mi * 16 + rh * 8 + (lane >> 2);
            float tot = sSum[r] + sSum[64 + r] + sSum[128 + r] + sSum[192 + r];
            float tq  = sSq[r]  + sSq[64 + r]  + sSq[128 + r]  + sSq[192 + r];
            float mu = tot * (1.f / 256.f);
            float rstd = rsqrtf(tq * (1.f / 256.f) - mu * mu + 1e-5f);
            int rG = mBase + r;
            float la = 0.f;
            #pragma unroll
            for (int nj = 0; nj < 8; nj++) {
                int col0 = nw * 64 + nj * 8 + 2 * (lane & 3);
                float v0 = acc[mi][nj][rh * 2 + 0], v1 = acc[mi][nj][rh * 2 + 1];
                float o0 = fmaxf(0.f, fmaf((v0 - mu) * rstd, par[256 + col0],     par[512 + col0]));
                float o1 = fmaxf(0.f, fmaf((v1 - mu) * rstd, par[256 + col0 + 1], par[512 + col0 + 1]));
                if (PH == 0) {
                    __half2 hx = __floats2half2_rn(o0, o1);
                    int prow = rG + 1;
                    uint32_t byte = (uint32_t)(2 * (col0 & 63)) ^ (uint32_t)((prow & 7) << 4);
                    *reinterpret_cast<uint32_t*>(g_h1a + (size_t)nw * PLANE_B
                        + (size_t)prow * 128 + byte) = *reinterpret_cast<uint32_t*>(&hx);
                } else {
                    la = fmaf(o0, par[768 + col0], la);
                    la = fmaf(o1, par[768 + col0 + 1], la);
                }
            }
            lacc[mi][rh] = la;
        }

    if (PH == 1) {
        #pragma unroll
        for (int mi = 0; mi < 2; mi++)
            #pragma unroll
            for (int rh = 0; rh < 2; rh++) {
                float la = lacc[mi][rh];
                la += __shfl_xor_sync(0xffffffffu, la, 1);
                la += __shfl_xor_sync(0xffffffffu, la, 2);
                if ((lane & 3) == 0)
                    sLin[nw * 64 + mw * 32 + mi * 16 + rh * 8 + (lane >> 2)] = la;
            }
        __syncthreads();
        if (nw == 0 && (lane & 3) == 0) {
            #pragma unroll
            for (int mi = 0; mi < 2; mi++)
                #pragma unroll
                for (int rh = 0; rh < 2; rh++) {
                    int r = mw * 32 + mi * 16 + rh * 8 + (lane >> 2);
                    float t = sLin[r] + sLin[64 + r] + sLin[128 + r] + sLin[192 + r];
                    pred[mBase + r] = fmaxf(0.f, t + lbp[0]);
                }
        }
    }
}

// ---- fused conv0 + conv1 persistent kernel (single wave, neighbor flag sync) ----
__global__ __launch_bounds__(256, 2) void fused_conv_k(
    const float* __restrict__ b1, const float* __restrict__ g1, const float* __restrict__ be1,
    const float* __restrict__ b2, const float* __restrict__ g2, const float* __restrict__ be2,
    const float* __restrict__ lw, const float* __restrict__ lbp, float* __restrict__ pred)
{
    extern __shared__ char smem[];
    const uint32_t sb0 = smem_u32(smem);
    const uint32_t tiles = (sb0 + 127) & ~127u;
    char* smc = smem + (tiles - sb0);
    float* sPar = (float*)(smc + OFF_PAR);
    float* sSum = (float*)(smc + OFF_SUM);
    float* sSq  = (float*)(smc + OFF_SQ);
    float* sLin = (float*)(smc + OFF_LIN);
    const uint32_t mbF = tiles + OFF_MBAR;
    const int tid = threadIdx.x, lane = tid & 31, warp = tid >> 5;
    const int mw = warp >> 2, nw = warp & 3;
    const int bid = blockIdx.x;
    const int mBase = bid * 64;

    int base = 0;
    if (tid == 0) base = g_flag[bid];      // own counter: only we increment it

    sPar[tid] = b1[tid];        sPar[256 + tid] = g1[tid];
    sPar[512 + tid] = be1[tid]; sPar[768 + tid] = 0.f;
    sPar[1024 + tid] = b2[tid]; sPar[1280 + tid] = g2[tid];
    sPar[1536 + tid] = be2[tid]; sPar[1792 + tid] = lw[tid];
    if (tid == 0) {
        MBAR_INIT(mbF, 1); MBAR_INIT(mbF + 8, 1);
        MBAR_INIT(mbF + 16, 8); MBAR_INIT(mbF + 24, 8);
    }
    __syncthreads();

    int pha[2] = {0, 0}, eph[2] = {0, 0};

    // phase 0: x -> h1 (writes g_h1a; also prefetches W2 during its epilogue)
    conv_phase<0>(smc, tiles, g_xa, g_w1s, mBase, tid, lane, mw, nw,
                  pha, eph, sPar, sSum, sSq, sLin, pred, lbp, false);

    // publish h1 tile; wait for neighbors; then issue phase-1 A copies
    __threadfence();
    __syncthreads();
    if (tid == 0) {
        atomicExch(&g_flag[bid], base + 1);
        const int tgt = base + 1;
        if (bid > 0)   while (ld_acq(&g_flag[bid - 1]) != tgt) __nanosleep(32);
        if (bid < 255) while (ld_acq(&g_flag[bid + 1]) != tgt) __nanosleep(32);
        #pragma unroll
        for (int j = 0; j < 2; j++)        // A copies (tx accumulates onto STG expect)
            bulk_cp(tiles + j * STG, g_h1a + (size_t)j * PLANE_B + (size_t)mBase * 128,
                    A_TILE, mbF + 8 * j);
    }

    // phase 1: h1 -> pred
    conv_phase<1>(smc, tiles, g_h1a, g_w2s, mBase, tid, lane, mw, nw,
                  pha, eph, sPar + 1024, sSum, sSq, sLin, pred, lbp, true);
}

// ---- rowmap + gather (unchanged, proven) ----
__global__ __launch_bounds__(512) void rowmap_k(const float* __restrict__ target, int L) {
    int b = blockIdx.x, s = threadIdx.x;
    int lane = s & 31, wp = s >> 5;
    int d = (int)rintf(target[b * 512 + s]);
    int v = d;
    #pragma unroll
    for (int o = 1; o < 32; o <<= 1) {
        int t = __shfl_up_sync(0xffffffffu, v, o);
        if (lane >= o) v += t;
    }
    __shared__ int wsum[16];
    if (lane == 31) wsum[wp] = v;
    __syncthreads();
    if (s < 16) {
        int w = wsum[s];
        #pragma unroll
        for (int o = 1; o < 16; o <<= 1) {
            int t = __shfl_up_sync(0x0000ffffu, w, o);
            if (s >= o) w += t;
        }
        wsum[s] = w;
    }
    __syncthreads();
    int end = v + (wp ? wsum[wp - 1] : 0);
    int start = end - d;
    int* rm = g_rowmap + (size_t)b * L;
    for (int l = s; l < L; l += 512) rm[l] = -1;
    __syncthreads();
    if (start < L) {
        int e = min(end, L);
        for (int l = start; l < e; ++l) rm[l] = s;
    }
}

__global__ __launch_bounds__(256) void gather_k(const float* __restrict__ x,
                                                float* __restrict__ out, int L) {
    int rowId = blockIdx.x * 4 + (threadIdx.x >> 6);
    if (rowId >= B_ * L) return;
    int t = threadIdx.x & 63;
    int b = rowId / L;
    int s = g_rowmap[rowId];
    float4 v = make_float4(0.f, 0.f, 0.f, 0.f);
    if (s >= 0)
        v = *reinterpret_cast<const float4*>(x + (size_t)((b << 9) + s) * D_ + (t << 2));
    *reinterpret_cast<float4*>(out + (size_t)rowId * D_ + (t << 2)) = v;
}

extern "C" void kernel_launch(void* const* d_in, const int* in_sizes, int n_in,
                              void* d_out, int out_size) {
    const float* x   = (const float*)d_in[0];
    const float* tgt = (const float*)d_in[1];
    const float* c1w = (const float*)d_in[2];
    const float* c1b = (const float*)d_in[3];
    const float* c2w = (const float*)d_in[4];
    const float* c2b = (const float*)d_in[5];
    const float* n1g = (const float*)d_in[6];
    const float* n1b = (const float*)d_in[7];
    const float* n2g = (const float*)d_in[8];
    const float* n2b = (const float*)d_in[9];
    const float* lw  = (const float*)d_in[10];
    const float* lb  = (const float*)d_in[11];

    float* out = (float*)d_out;
    int L = (out_size - B_ * S_) / (B_ * D_);
    float* pred = out + (size_t)B_ * L * D_;

    static cudaStream_t sHi = nullptr, sLo = nullptr;
    static cudaEvent_t evF = nullptr, evW = nullptr, evH = nullptr, evJ = nullptr;
    if (sHi == nullptr) {
        int pLo, pHi;
        cudaDeviceGetStreamPriorityRange(&pLo, &pHi);
        cudaStreamCreateWithPriority(&sHi, cudaStreamNonBlocking, pHi);
        cudaStreamCreateWithPriority(&sLo, cudaStreamNonBlocking, pLo);
        cudaEventCreateWithFlags(&evF, cudaEventDisableTiming);
        cudaEventCreateWithFlags(&evW, cudaEventDisableTiming);
        cudaEventCreateWithFlags(&evH, cudaEventDisableTiming);
        cudaEventCreateWithFlags(&evJ, cudaEventDisableTiming);
        cudaFuncSetAttribute(fused_conv_k, cudaFuncAttributeMaxDynamicSharedMemorySize, SMEM_TOTAL);
    }

    // fork
    cudaEventRecord(evF, 0);
    cudaStreamWaitEvent(sHi, evF, 0);
    cudaStreamWaitEvent(sLo, evF, 0);

    // low-priority branch: weight prep + length regulator
    cvt_w_k<<<2 * F_ * KK_ / 256, 256, 0, sLo>>>(c1w, c2w);
    cudaEventRecord(evW, sLo);
    rowmap_k<<<B_, 512, 0, sLo>>>(tgt, L);
    gather_k<<<(B_ * L + 3) / 4, 256, 0, sLo>>>(x, out, L);
    cudaEventRecord(evJ, sLo);

    // high-priority branch: duration predictor (single fused conv kernel)
    cvt_x_k<<<BS_ * 16 / 256, 256, 0, sHi>>>(x);
    cudaStreamWaitEvent(sHi, evW, 0);
    fused_conv_k<<<256, 256, SMEM_TOTAL, sHi>>>(c1b, n1g, n1b, c2b, n2g, n2b, lw, lb, pred);
    cudaEventRecord(evH, sHi);

    // join
    cudaStreamWaitEvent(0, evH, 0);
    cudaStreamWaitEvent(0, evJ, 0);
}

// round 12
// speedup vs baseline: 7.4224x; 1.0907x over previous
#include <cuda_runtime.h>
#include <cuda_fp16.h>
#include <cstdint>

#define B_  32
#define S_  512
#define D_  256
#define F_  256
#define BS_ 16384
#define KK_ 768
#define NCH 12
#define W_TILE 32768               // 256 rows x 128B, pre-swizzled
#define OFF_A   (2*W_TILE)         // 65536: persistent A region, 66 rows x 512B
#define OFF_PAR (OFF_A + 66*512)   // 99328
#define OFF_SUM (OFF_PAR + 8192)   // 107520
#define OFF_SQ  (OFF_SUM + 1024)
#define OFF_LIN (OFF_SQ  + 1024)
#define OFF_MBAR (OFF_LIN + 1024)  // 110592
#define SMEM_TOTAL (OFF_MBAR + 64 + 128)   // 110784 -> 2 CTAs/SM

__device__ char g_w1s[NCH*W_TILE];
__device__ char g_w2s[NCH*W_TILE];
__device__ char g_h1halo[256*1024];        // [bid][2][512B] swizzled rows
__device__ int  g_rowmap[B_*4608];
__device__ int  g_flag[256];               // monotonic per-launch counters

__device__ __forceinline__ uint32_t smem_u32(const void* p) {
    uint32_t a;
    asm("{ .reg .u64 t; cvta.to.shared.u64 t, %1; cvt.u32.u64 %0, t; }" : "=r"(a) : "l"(p));
    return a;
}
#define MBAR_INIT(a, c) asm volatile("mbarrier.init.shared.b64 [%0], %1;" :: "r"((uint32_t)(a)), "r"((uint32_t)(c)) : "memory")
#define MBAR_EXPECT(a, b) asm volatile("mbarrier.arrive.expect_tx.shared.b64 _, [%0], %1;" :: "r"((uint32_t)(a)), "r"((uint32_t)(b)) : "memory")
#define MBAR_ARRIVE(a) asm volatile("mbarrier.arrive.shared.b64 _, [%0];" :: "r"((uint32_t)(a)) : "memory")
#define MBAR_WAIT(a, ph) do { \
    uint32_t _m = (uint32_t)(a), _p = (uint32_t)(ph), _d; \
    asm volatile("{ .reg .pred p; mbarrier.try_wait.parity.acquire.cta.shared::cta.b64 p, [%1], %2; selp.b32 %0, 1, 0, p; }" \
        : "=r"(_d) : "r"(_m), "r"(_p) : "memory"); \
    if (!_d) { asm volatile("{ .reg .pred P1;\nWL_%=:\n" \
        "mbarrier.try_wait.parity.acquire.cta.shared::cta.b64 P1, [%0], %1, 0x989680;\n" \
        "@P1 bra.uni WD_%=;\nbra.uni WL_%=;\nWD_%=:\n}" :: "r"(_m), "r"(_p) : "memory"); } \
} while (0)
__device__ __forceinline__ void bulk_cp(uint32_t dst, const void* src, uint32_t bytes, uint32_t mbar) {
    asm volatile("cp.async.bulk.shared::cta.global.mbarrier::complete_tx::bytes [%0], [%1], %2, [%3];"
        :: "r"(dst), "l"(src), "r"(bytes), "r"(mbar) : "memory");
}
__device__ __forceinline__ void ldsm_x4(uint32_t* r, uint32_t a) {
    asm volatile("ldmatrix.sync.aligned.m8n8.x4.shared.b16 {%0,%1,%2,%3}, [%4];"
        : "=r"(r[0]), "=r"(r[1]), "=r"(r[2]), "=r"(r[3]) : "r"(a));
}
__device__ __forceinline__ void mma_f16(float* d, const uint32_t* a, const uint32_t* b) {
    asm volatile("mma.sync.aligned.m16n8k16.row.col.f32.f16.f16.f32 "
        "{%0,%1,%2,%3}, {%4,%5,%6,%7}, {%8,%9}, {%0,%1,%2,%3};"
        : "+f"(d[0]), "+f"(d[1]), "+f"(d[2]), "+f"(d[3])
        : "r"(a[0]), "r"(a[1]), "r"(a[2]), "r"(a[3]), "r"(b[0]), "r"(b[1]));
}
__device__ __forceinline__ int ld_acq(const int* p) {
    int v; asm volatile("ld.acquire.gpu.global.s32 %0, [%1];" : "=r"(v) : "l"(p)); return v;
}

// ---- prep: weights -> chunked+swizzled ----
__global__ __launch_bounds__(256) void cvt_w_k(const float* __restrict__ w1,
                                               const float* __restrict__ w2) {
    int gid = blockIdx.x * 256 + threadIdx.x;
    int ph = gid >= F_ * KK_;
    int idx = ph ? gid - F_ * KK_ : gid;
    int f = idx / 768, rem = idx - f * 768;
    int tap = rem >> 8, c = rem & 255;
    int kk = tap * 256 + c;
    int chunk = kk >> 6, kc = kk & 63;
    const float* w = ph ? w2 : w1;
    __half hv = __float2half(w[f * 768 + c * 3 + tap]);
    uint32_t byte = (uint32_t)(2 * kc) ^ (uint32_t)((f & 7) << 4);
    *reinterpret_cast<__half*>((ph ? g_w2s : g_w1s)
        + (size_t)chunk * W_TILE + (size_t)f * 128 + byte) = hv;
}

// ---- one conv phase main loop + epilogue ----
template<int PH>
__device__ __forceinline__ void conv_phase(
    char* smc, uint32_t tiles, const char* Wst,
    int mBase, int bid, int tid, int lane, int mw, int nw,
    int* pha, int* eph, const float* par,
    float* sSum, float* sSq, float* sLin,
    float* pred, const float* lbp)
{
    const uint32_t mbF = tiles + OFF_MBAR, mbE = mbF + 16;
    const uint32_t aA = tiles + OFF_A;

    float acc[2][8][4];
    #pragma unroll
    for (int a = 0; a < 2; a++)
        #pragma unroll
        for (int b = 0; b < 8; b++)
            #pragma unroll
            for (int c = 0; c < 4; c++) acc[a][b][c] = 0.f;

    for (int i = 0; i < NCH; i++) {
        const int st = i & 1;
        const int tap = i >> 2;
        const int cg = i & 3;
        if (tid == 0 && i >= 1 && i + 1 < NCH) {
            const int st2 = st ^ 1;
            MBAR_WAIT(mbE + 8 * st2, eph[st2]); eph[st2] ^= 1;
            MBAR_EXPECT(mbF + 8 * st2, W_TILE);
            bulk_cp(tiles + st2 * W_TILE, Wst + (size_t)(i + 1) * W_TILE, W_TILE, mbF + 8 * st2);
        }
        MBAR_WAIT(mbF + 8 * st, pha[st]); pha[st] ^= 1;
        const uint32_t wT = tiles + st * W_TILE;

        #pragma unroll
        for (int ks = 0; ks < 4; ks++) {
            uint32_t bf[8][2];
            #pragma unroll
            for (int njp = 0; njp < 4; njp++) {
                int f = nw * 64 + (2 * njp + ((lane >> 4) & 1)) * 8 + (lane & 7);
                int kseg = ks * 2 + ((lane >> 3) & 1);
                uint32_t ad = wT + (uint32_t)f * 128 + (uint32_t)((kseg ^ (f & 7)) << 4);
                uint32_t r[4];
                ldsm_x4(r, ad);
                bf[2 * njp][0] = r[0]; bf[2 * njp][1] = r[1];
                bf[2 * njp + 1][0] = r[2]; bf[2 * njp + 1][1] = r[3];
            }
            #pragma unroll
            for (int mi = 0; mi < 2; mi++) {
                int p = mw * 32 + mi * 16 + (lane & 7) + ((lane >> 3) & 1) * 8 + tap;
                int kseg = ks * 2 + ((lane >> 4) & 1);
                uint32_t ad = aA + (uint32_t)p * 512 + (uint32_t)cg * 128
                              + (uint32_t)((kseg ^ (p & 7)) << 4);
                uint32_t af[4];
                ldsm_x4(af, ad);
                #pragma unroll
                for (int nj = 0; nj < 8; nj++)
                    mma_f16(acc[mi][nj], af, bf[nj]);
            }
        }
        if (lane == 0) MBAR_ARRIVE(mbE + 8 * st);
    }
    __syncthreads();

    // ---- PH=0 hook: drain empties, prefetch W2 chunks 0/1 into stages ----
    if (PH == 0 && tid == 0) {
        MBAR_WAIT(mbE, eph[0]); eph[0] ^= 1;
        MBAR_WAIT(mbE + 8, eph[1]); eph[1] ^= 1;
        #pragma unroll
        for (int j = 0; j < 2; j++) {
            MBAR_EXPECT(mbF + 8 * j, W_TILE);
            bulk_cp(tiles + j * W_TILE, g_w2s + (size_t)j * W_TILE, W_TILE, mbF + 8 * j);
        }
    }

    // ---- epilogue: bias + LN ----
    #pragma unroll
    for (int mi = 0; mi < 2; mi++)
        #pragma unroll
        for (int rh = 0; rh < 2; rh++) {
            float s = 0.f, q = 0.f;
            #pragma unroll
            for (int nj = 0; nj < 8; nj++)
                #pragma unroll
                for (int h = 0; h < 2; h++) {
                    int col = nw * 64 + nj * 8 + 2 * (lane & 3) + h;
                    float v = acc[mi][nj][rh * 2 + h] + par[col];
                    acc[mi][nj][rh * 2 + h] = v;
                    s += v; q = fmaf(v, v, q);
                }
            s += __shfl_xor_sync(0xffffffffu, s, 1); s += __shfl_xor_sync(0xffffffffu, s, 2);
            q += __shfl_xor_sync(0xffffffffu, q, 1); q += __shfl_xor_sync(0xffffffffu, q, 2);
            if ((lane & 3) == 0) {
                int r = mw * 32 + mi * 16 + rh * 8 + (lane >> 2);
                sSum[nw * 64 + r] = s; sSq[nw * 64 + r] = q;
            }
        }
    __syncthreads();

    float lacc[2][2];
    #pragma unroll
    for (int mi = 0; mi < 2; mi++)
        #pragma unroll
        for (int rh = 0; rh < 2; rh++) {
            int r = mw * 32 + mi * 16 + rh * 8 + (lane >> 2);
            float tot = sSum[r] + sSum[64 + r] + sSum[128 + r] + sSum[192 + r];
            float tq  = sSq[r]  + sSq[64 + r]  + sSq[128 + r]  + sSq[192 + r];
            float mu = tot * (1.f / 256.f);
            float rstd = rsqrtf(tq * (1.f / 256.f) - mu * mu + 1e-5f);
            const int p = r + 1;
            float la = 0.f;
            #pragma unroll
            for (int nj = 0; nj < 8; nj++) {
                int col0 = nw * 64 + nj * 8 + 2 * (lane & 3);
                float v0 = acc[mi][nj][rh * 2 + 0], v1 = acc[mi][nj][rh * 2 + 1];
                float o0 = fmaxf(0.f, fmaf((v0 - mu) * rstd, par[256 + col0],     par[512 + col0]));
                float o1 = fmaxf(0.f, fmaf((v1 - mu) * rstd, par[256 + col0 + 1], par[512 + col0 + 1]));
                if (PH == 0) {
                    __half2 hxv = __floats2half2_rn(o0, o1);
                    uint32_t hx = *reinterpret_cast<uint32_t*>(&hxv);
                    uint32_t off = (uint32_t)(col0 >> 6) * 128
                                 + (uint32_t)((((col0 >> 3) & 7) ^ (p & 7)) << 4)
                                 + (uint32_t)((col0 & 7) * 2);
                    *reinterpret_cast<uint32_t*>(smc + OFF_A + p * 512 + off) = hx;
                    if (r == 0)
                        *reinterpret_cast<uint32_t*>(g_h1halo + bid * 1024 + off) = hx;
                    if (r == 63)
                        *reinterpret_cast<uint32_t*>(g_h1halo + bid * 1024 + 512 + off) = hx;
                } else {
                    la = fmaf(o0, par[768 + col0], la);
                    la = fmaf(o1, par[768 + col0 + 1], la);
                }
            }
            lacc[mi][rh] = la;
        }

    if (PH == 1) {
        #pragma unroll
        for (int mi = 0; mi < 2; mi++)
            #pragma unroll
            for (int rh = 0; rh < 2; rh++) {
                float la = lacc[mi][rh];
                la += __shfl_xor_sync(0xffffffffu, la, 1);
                la += __shfl_xor_sync(0xffffffffu, la, 2);
                if ((lane & 3) == 0)
                    sLin[nw * 64 + mw * 32 + mi * 16 + rh * 8 + (lane >> 2)] = la;
            }
        __syncthreads();
        if (nw == 0 && (lane & 3) == 0) {
            #pragma unroll
            for (int mi = 0; mi < 2; mi++)
                #pragma unroll
                for (int rh = 0; rh < 2; rh++) {
                    int r = mw * 32 + mi * 16 + rh * 8 + (lane >> 2);
                    float t = sLin[r] + sLin[64 + r] + sLin[128 + r] + sLin[192 + r];
                    pred[mBase + r] = fmaxf(0.f, t + lbp[0]);
                }
        }
    }
}

// ---- fused conv0 + conv1 persistent kernel, in-kernel x conversion ----
__global__ __launch_bounds__(256, 2) void fused_conv_k(
    const float* __restrict__ x,
    const float* __restrict__ b1, const float* __restrict__ g1, const float* __restrict__ be1,
    const float* __restrict__ b2, const float* __restrict__ g2, const float* __restrict__ be2,
    const float* __restrict__ lw, const float* __restrict__ lbp, float* __restrict__ pred)
{
    extern __shared__ char smem[];
    const uint32_t sb0 = smem_u32(smem);
    const uint32_t tiles = (sb0 + 127) & ~127u;
    char* smc = smem + (tiles - sb0);
    float* sPar = (float*)(smc + OFF_PAR);
    float* sSum = (float*)(smc + OFF_SUM);
    float* sSq  = (float*)(smc + OFF_SQ);
    float* sLin = (float*)(smc + OFF_LIN);
    const uint32_t mbF = tiles + OFF_MBAR;
    const int tid = threadIdx.x, lane = tid & 31, warp = tid >> 5;
    const int mw = warp >> 2, nw = warp & 3;
    const int bid = blockIdx.x;
    const int mBase = bid * 64;
    const bool fix0 = ((mBase & 511) == 0);
    const bool fix2 = (((mBase + 64) & 511) == 0);

    int base = 0;
    if (tid == 0) base = g_flag[bid];

    sPar[tid] = b1[tid];        sPar[256 + tid] = g1[tid];
    sPar[512 + tid] = be1[tid]; sPar[768 + tid] = 0.f;
    sPar[1024 + tid] = b2[tid]; sPar[1280 + tid] = g2[tid];
    sPar[1536 + tid] = be2[tid]; sPar[1792 + tid] = lw[tid];
    if (tid == 0) {
        MBAR_INIT(mbF, 1); MBAR_INIT(mbF + 8, 1);
        MBAR_INIT(mbF + 16, 8); MBAR_INIT(mbF + 24, 8);
    }
    __syncthreads();

    // issue W1 chunks 0,1 (overlaps x conversion below)
    if (tid == 0) {
        #pragma unroll
        for (int j = 0; j < 2; j++) {
            MBAR_EXPECT(mbF + 8 * j, W_TILE);
            bulk_cp(tiles + j * W_TILE, g_w1s + (size_t)j * W_TILE, W_TILE, mbF + 8 * j);
        }
    }

    // convert own x rows (with halo) fp32 -> fp16 swizzled into persistent A region
    for (int it = tid; it < 66 * 32; it += 256) {
        int row = it >> 5, s = it & 31;
        bool zero = (row == 0 && fix0) || (row == 65 && fix2);
        float4 v0 = make_float4(0.f, 0.f, 0.f, 0.f), v1 = v0;
        if (!zero) {
            const float4* src = reinterpret_cast<const float4*>(
                x + (size_t)(mBase - 1 + row) * 256 + s * 8);
            v0 = src[0]; v1 = src[1];
        }
        __half2 a = __floats2half2_rn(v0.x, v0.y), b = __floats2half2_rn(v0.z, v0.w);
        __half2 c = __floats2half2_rn(v1.x, v1.y), d = __floats2half2_rn(v1.z, v1.w);
        uint4 o = make_uint4(*(uint32_t*)&a, *(uint32_t*)&b, *(uint32_t*)&c, *(uint32_t*)&d);
        *reinterpret_cast<uint4*>(smc + OFF_A + row * 512 + (s >> 3) * 128
            + (((s & 7) ^ (row & 7)) << 4)) = o;
    }
    __syncthreads();

    int pha[2] = {0, 0}, eph[2] = {0, 0};

    // phase 0: x -> h1 (h1 written to smem A region + 2 halo rows to gmem)
    conv_phase<0>(smc, tiles, g_w1s, mBase, bid, tid, lane, mw, nw,
                  pha, eph, sPar, sSum, sSq, sLin, pred, lbp);

    // publish halo rows; wait only for needed neighbors; fill p=0 / p=65
    __threadfence();
    __syncthreads();
    if (tid == 0) {
        atomicExch(&g_flag[bid], base + 1);
        const int tgt = base + 1;
        if (!fix0) while (ld_acq(&g_flag[bid - 1]) != tgt) __nanosleep(32);
        if (!fix2) while (ld_acq(&g_flag[bid + 1]) != tgt) __nanosleep(32);
    }
    __syncthreads();
    if (warp == 0) {
        uint4 v = make_uint4(0, 0, 0, 0);
        if (!fix0) v = *reinterpret_cast<const uint4*>(g_h1halo + (bid - 1) * 1024 + 512 + lane * 16);
        *reinterpret_cast<uint4*>(smc + OFF_A + lane * 16) = v;
    } else if (warp == 1) {
        uint4 v = make_uint4(0, 0, 0, 0);
        if (!fix2) v = *reinterpret_cast<const uint4*>(g_h1halo + (bid + 1) * 1024 + lane * 16);
        *reinterpret_cast<uint4*>(smc + OFF_A + 65 * 512 + lane * 16) = v;
    }
    __syncthreads();

    // phase 1: h1 -> pred
    conv_phase<1>(smc, tiles, g_w2s, mBase, bid, tid, lane, mw, nw,
                  pha, eph, sPar + 1024, sSum, sSq, sLin, pred, lbp);
}

// ---- rowmap + gather (unchanged, proven) ----
__global__ __launch_bounds__(512) void rowmap_k(const float* __restrict__ target, int L) {
    int b = blockIdx.x, s = threadIdx.x;
    int lane = s & 31, wp = s >> 5;
    int d = (int)rintf(target[b * 512 + s]);
    int v = d;
    #pragma unroll
    for (int o = 1; o < 32; o <<= 1) {
        int t = __shfl_up_sync(0xffffffffu, v, o);
        if (lane >= o) v += t;
    }
    __shared__ int wsum[16];
    if (lane == 31) wsum[wp] = v;
    __syncthreads();
    if (s < 16) {
        int w = wsum[s];
        #pragma unroll
        for (int o = 1; o < 16; o <<= 1) {
            int t = __shfl_up_sync(0x0000ffffu, w, o);
            if (s >= o) w += t;
        }
        wsum[s] = w;
    }
    __syncthreads();
    int end = v + (wp ? wsum[wp - 1] : 0);
    int start = end - d;
    int* rm = g_rowmap + (size_t)b * L;
    for (int l = s; l < L; l += 512) rm[l] = -1;
    __syncthreads();
    if (start < L) {
        int e = min(end, L);
        for (int l = start; l < e; ++l) rm[l] = s;
    }
}

__global__ __launch_bounds__(256) void gather_k(const float* __restrict__ x,
                                                float* __restrict__ out, int L) {
    int rowId = blockIdx.x * 4 + (threadIdx.x >> 6);
    if (rowId >= B_ * L) return;
    int t = threadIdx.x & 63;
    int b = rowId / L;
    int s = g_rowmap[rowId];
    float4 v = make_float4(0.f, 0.f, 0.f, 0.f);
    if (s >= 0)
        v = *reinterpret_cast<const float4*>(x + (size_t)((b << 9) + s) * D_ + (t << 2));
    *reinterpret_cast<float4*>(out + (size_t)rowId * D_ + (t << 2)) = v;
}

extern "C" void kernel_launch(void* const* d_in, const int* in_sizes, int n_in,
                              void* d_out, int out_size) {
    const float* x   = (const float*)d_in[0];
    const float* tgt = (const float*)d_in[1];
    const float* c1w = (const float*)d_in[2];
    const float* c1b = (const float*)d_in[3];
    const float* c2w = (const float*)d_in[4];
    const float* c2b = (const float*)d_in[5];
    const float* n1g = (const float*)d_in[6];
    const float* n1b = (const float*)d_in[7];
    const float* n2g = (const float*)d_in[8];
    const float* n2b = (const float*)d_in[9];
    const float* lw  = (const float*)d_in[10];
    const float* lb  = (const float*)d_in[11];

    float* out = (float*)d_out;
    int L = (out_size - B_ * S_) / (B_ * D_);
    float* pred = out + (size_t)B_ * L * D_;

    static cudaStream_t sHi = nullptr, sLo = nullptr;
    static cudaEvent_t evF = nullptr, evW = nullptr, evH = nullptr, evJ = nullptr;
    if (sHi == nullptr) {
        int pLo, pHi;
        cudaDeviceGetStreamPriorityRange(&pLo, &pHi);
        cudaStreamCreateWithPriority(&sHi, cudaStreamNonBlocking, pHi);
        cudaStreamCreateWithPriority(&sLo, cudaStreamNonBlocking, pLo);
        cudaEventCreateWithFlags(&evF, cudaEventDisableTiming);
        cudaEventCreateWithFlags(&evW, cudaEventDisableTiming);
        cudaEventCreateWithFlags(&evH, cudaEventDisableTiming);
        cudaEventCreateWithFlags(&evJ, cudaEventDisableTiming);
        cudaFuncSetAttribute(fused_conv_k, cudaFuncAttributeMaxDynamicSharedMemorySize, SMEM_TOTAL);
    }

    // fork
    cudaEventRecord(evF, 0);
    cudaStreamWaitEvent(sHi, evF, 0);
    cudaStreamWaitEvent(sLo, evF, 0);

    // low-priority branch: weight prep + length regulator
    cvt_w_k<<<2 * F_ * KK_ / 256, 256, 0, sLo>>>(c1w, c2w);
    cudaEventRecord(evW, sLo);
    rowmap_k<<<B_, 512, 0, sLo>>>(tgt, L);
    gather_k<<<(B_ * L + 3) / 4, 256, 0, sLo>>>(x, out, L);
    cudaEventRecord(evJ, sLo);

    // high-priority branch: fused duration predictor
    cudaStreamWaitEvent(sHi, evW, 0);
    fused_conv_k<<<256, 256, SMEM_TOTAL, sHi>>>(x, c1b, n1g, n1b, c2b, n2g, n2b, lw, lb, pred);
    cudaEventRecord(evH, sHi);

    // join
    cudaStreamWaitEvent(0, evH, 0);
    cudaStreamWaitEvent(0, evJ, 0);
}